// round 3
// baseline (speedup 1.0000x reference)
#include <cuda_runtime.h>
#include <math.h>

// ---------------- problem constants ----------------
#define DIMC   512
#define NHEADS 16
#define HD     32
#define LHD    8
#define LDIM   128
#define NTOK   49
#define NB     2048
#define NWIN   64
#define MROWS  (NB*NTOK)        // 100352
#define NNSQ   (NTOK*NTOK)      // 2401

// ---------------- device scratch (no allocations allowed) ----------------
__device__ float g_q [NB*NHEADS*NTOK*HD];
__device__ float g_k [NB*NHEADS*NTOK*HD];
__device__ float g_v [NB*NHEADS*NTOK*HD];
__device__ float g_ql[NB*NHEADS*NTOK*LHD];
__device__ float g_kl[NB*NHEADS*NTOK*LHD];
__device__ float g_vl[NB*NHEADS*NTOK*LHD];
__device__ float g_xo[(size_t)MROWS*DIMC];
__device__ float g_dv[(size_t)MROWS*LDIM];
__device__ float g_relbias[NHEADS*NNSQ];
__device__ float g_W2t[DIMC*LDIM];
__device__ float g_b2 [DIMC];

// ---------------- prep kernels ----------------
__global__ void prep_bias_kernel(const int* __restrict__ rpi,
                                 const float* __restrict__ table) {
    int idx = blockIdx.x * 256 + threadIdx.x;
    if (idx < NHEADS * NNSQ) {
        int h = idx / NNSQ, ij = idx % NNSQ;
        g_relbias[idx] = table[rpi[ij] * NHEADS + h];
    }
}

// W2t[o][l] = gamma * sum_c dpw[c][l] * pw[o][c]
__global__ void prep_w2_kernel(const float* __restrict__ dpw,
                               const float* __restrict__ pw,
                               const float* __restrict__ gamma_p) {
    int o = blockIdx.x;        // 512
    int l = threadIdx.x;       // 128
    float s = 0.f;
    for (int c = 0; c < DIMC; c++)
        s += dpw[c * LDIM + l] * pw[o * DIMC + c];
    g_W2t[o * LDIM + l] = (*gamma_p) * s;
}

// b2[o] = pb[o] + gamma * sum_c dpb[c] * pw[o][c]
__global__ void prep_b2_kernel(const float* __restrict__ dpb,
                               const float* __restrict__ pw,
                               const float* __restrict__ pb,
                               const float* __restrict__ gamma_p) {
    int o = blockIdx.x * 256 + threadIdx.x;
    if (o < DIMC) {
        float s = 0.f;
        for (int c = 0; c < DIMC; c++) s += dpb[c] * pw[o * DIMC + c];
        g_b2[o] = pb[o] + (*gamma_p) * s;
    }
}

// ---------------- shared GEMM tile core ----------------
// C_tile[128x128] += A[128 x K] * B[128 x K]^T   (A row-major lda, B row-major ldb)
// 256 threads, 8x8 per thread (split as 2x float4 in each dim).
__device__ __forceinline__ void gemm_tile(const float* __restrict__ A, int lda,
                                          const float* __restrict__ Bw, int ldb,
                                          int K, float acc[8][8],
                                          float (*As)[132], float (*Bs)[132],
                                          int tid) {
    const int tm = tid >> 4, tn = tid & 15;
    const int lr = tid >> 2, lc = (tid & 3) * 4;
    for (int k0 = 0; k0 < K; k0 += 16) {
        float4 a0 = *(const float4*)(A + (size_t)lr        * lda + k0 + lc);
        float4 a1 = *(const float4*)(A + (size_t)(lr + 64) * lda + k0 + lc);
        float4 b0 = *(const float4*)(Bw + (size_t)lr        * ldb + k0 + lc);
        float4 b1 = *(const float4*)(Bw + (size_t)(lr + 64) * ldb + k0 + lc);
        As[lc + 0][lr]      = a0.x; As[lc + 1][lr]      = a0.y;
        As[lc + 2][lr]      = a0.z; As[lc + 3][lr]      = a0.w;
        As[lc + 0][lr + 64] = a1.x; As[lc + 1][lr + 64] = a1.y;
        As[lc + 2][lr + 64] = a1.z; As[lc + 3][lr + 64] = a1.w;
        Bs[lc + 0][lr]      = b0.x; Bs[lc + 1][lr]      = b0.y;
        Bs[lc + 2][lr]      = b0.z; Bs[lc + 3][lr]      = b0.w;
        Bs[lc + 0][lr + 64] = b1.x; Bs[lc + 1][lr + 64] = b1.y;
        Bs[lc + 2][lr + 64] = b1.z; Bs[lc + 3][lr + 64] = b1.w;
        __syncthreads();
        #pragma unroll
        for (int kk = 0; kk < 16; kk++) {
            float4 xa0 = *(const float4*)&As[kk][tm * 4];
            float4 xa1 = *(const float4*)&As[kk][64 + tm * 4];
            float4 xb0 = *(const float4*)&Bs[kk][tn * 4];
            float4 xb1 = *(const float4*)&Bs[kk][64 + tn * 4];
            float ra[8] = {xa0.x, xa0.y, xa0.z, xa0.w, xa1.x, xa1.y, xa1.z, xa1.w};
            float rb[8] = {xb0.x, xb0.y, xb0.z, xb0.w, xb1.x, xb1.y, xb1.z, xb1.w};
            #pragma unroll
            for (int i = 0; i < 8; i++)
                #pragma unroll
                for (int j = 0; j < 8; j++)
                    acc[i][j] += ra[i] * rb[j];
        }
        __syncthreads();
    }
}

// ---------------- GEMM1: fused qkv + lite projections, scatter epilogue ----------------
// cols 0..1535 -> qkv (j*512 + h*32 + d), cols 1536..1919 -> lite (j*128 + h*8 + d)
__global__ __launch_bounds__(256, 2)
void gemm1_kernel(const float* __restrict__ x,
                  const float* __restrict__ qkv_w, const float* __restrict__ qkv_b,
                  const float* __restrict__ qlw, const float* __restrict__ klw,
                  const float* __restrict__ vlw) {
    __shared__ __align__(16) float As[16][132];
    __shared__ __align__(16) float Bs[16][132];
    const int m0 = blockIdx.y * 128;
    const int n0 = blockIdx.x * 128;
    const int tid = threadIdx.x;

    const float* Bp;
    if (n0 < 1536)       Bp = qkv_w + (size_t)n0 * DIMC;
    else if (n0 == 1536) Bp = qlw;
    else if (n0 == 1664) Bp = klw;
    else                 Bp = vlw;

    float acc[8][8] = {};
    gemm_tile(x + (size_t)m0 * DIMC, DIMC, Bp, DIMC, DIMC, acc, As, Bs, tid);

    const int tm = tid >> 4, tn = tid & 15;
    #pragma unroll
    for (int i = 0; i < 8; i++) {
        int m = m0 + ((i < 4) ? (tm * 4 + i) : (64 + tm * 4 + (i - 4)));
        int b = m / NTOK, n = m - b * NTOK;
        #pragma unroll
        for (int j = 0; j < 8; j++) {
            int c = n0 + ((j < 4) ? (tn * 4 + j) : (64 + tn * 4 + (j - 4)));
            float val = acc[i][j];
            if (n0 < 1536) {
                val += qkv_b[c];
                int jj = c >> 9, hh = (c >> 5) & 15, d = c & 31;
                float* dst = (jj == 0) ? g_q : ((jj == 1) ? g_k : g_v);
                dst[((size_t)(b * NHEADS + hh) * NTOK + n) * HD + d] = val;
            } else {
                int cc = c - 1536;
                int jj = cc >> 7, hh = (cc >> 3) & 15, d = cc & 7;
                float* dst = (jj == 0) ? g_ql : ((jj == 1) ? g_kl : g_vl);
                dst[((size_t)(b * NHEADS + hh) * NTOK + n) * LHD + d] = val;
            }
        }
    }
}

// ---------------- fused dual attention, one block per (b,h) ----------------
__global__ __launch_bounds__(256)
void attn_kernel(const float* __restrict__ mask,
                 const float* __restrict__ lam1p,
                 const float* __restrict__ lam2p) {
    __shared__ float sq[NTOK * HD];
    __shared__ float skT[HD * NTOK];     // transposed: [d][j]
    __shared__ float sv[NTOK * HD];
    __shared__ float sql[NTOK * LHD];
    __shared__ float sklT[LHD * NTOK];   // transposed
    __shared__ float svl[NTOK * LHD];
    __shared__ float sp[NNSQ];
    __shared__ float spl[NNSQ];

    const int bid = blockIdx.x;
    const int b = bid >> 4, h = bid & 15;
    const int win = b & (NWIN - 1);
    const int tid = threadIdx.x;
    const size_t base  = (size_t)bid * (NTOK * HD);
    const size_t basel = (size_t)bid * (NTOK * LHD);

    for (int idx = tid; idx < NTOK * HD; idx += 256) {
        sq[idx] = g_q[base + idx];
        int j = idx >> 5, d = idx & 31;
        skT[d * NTOK + j] = g_k[base + idx];
        sv[idx] = g_v[base + idx];
    }
    for (int idx = tid; idx < NTOK * LHD; idx += 256) {
        sql[idx] = g_ql[basel + idx];
        int j = idx >> 3, d = idx & 7;
        sklT[d * NTOK + j] = g_kl[basel + idx];
        svl[idx] = g_vl[basel + idx];
    }
    __syncthreads();

    const float scale   = 0.17677669529663687f;  // 32^-0.5
    const float scale_l = 0.35355339059327373f;  // 8^-0.5
    const float* bias_h = g_relbias + h * NNSQ;
    const float* mask_w = mask + win * NNSQ;

    for (int idx = tid; idx < NNSQ; idx += 256) {
        int i = idx / NTOK, j = idx - i * NTOK;
        float bm = bias_h[idx] + mask_w[idx];
        float dot = 0.f;
        #pragma unroll
        for (int d = 0; d < HD; d++) dot += sq[i * HD + d] * skT[d * NTOK + j];
        float dotl = 0.f;
        #pragma unroll
        for (int d = 0; d < LHD; d++) dotl += sql[i * LHD + d] * sklT[d * NTOK + j];
        sp[idx]  = dot  * scale   + bm;
        spl[idx] = dotl * scale_l + bm;
    }
    __syncthreads();

    if (tid < 2 * NTOK) {
        float* row = ((tid < NTOK) ? sp : spl) + ((tid < NTOK) ? tid : tid - NTOK) * NTOK;
        float mx = row[0];
        for (int j = 1; j < NTOK; j++) mx = fmaxf(mx, row[j]);
        float s = 0.f;
        for (int j = 0; j < NTOK; j++) { float e = expf(row[j] - mx); row[j] = e; s += e; }
        float inv = 1.f / s;
        for (int j = 0; j < NTOK; j++) row[j] *= inv;
    }
    __syncthreads();

    const float lam1 = 1.f / (1.f + expf(-*lam1p));
    const float lam2 = 1.f / (1.f + expf(-*lam2p));

    for (int o = tid; o < NTOK * HD; o += 256) {
        int i = o >> 5, d = o & 31;
        float s = 0.f;
        #pragma unroll
        for (int j = 0; j < NTOK; j++) s += sp[i * NTOK + j] * sv[j * HD + d];
        g_xo[((size_t)(b * NTOK + i)) * DIMC + h * HD + d] = s;
    }
    for (int o = tid; o < NTOK * LHD; o += 256) {
        int i = o >> 3, d = o & 7;
        float s = 0.f;
        #pragma unroll
        for (int j = 0; j < NTOK; j++)
            s += (lam1 * spl[i * NTOK + j] - lam2 * sp[i * NTOK + j]) * svl[j * LHD + d];
        g_dv[((size_t)(b * NTOK + i)) * LDIM + h * LHD + d] = s;
    }
}

// ---------------- GEMM3: out = xo@Wp^T + dv@W2t^T + b2 ----------------
__global__ __launch_bounds__(256, 2)
void gemm3_kernel(float* __restrict__ out, const float* __restrict__ pw) {
    __shared__ __align__(16) float As[16][132];
    __shared__ __align__(16) float Bs[16][132];
    const int m0 = blockIdx.y * 128;
    const int n0 = blockIdx.x * 128;
    const int tid = threadIdx.x;

    float acc[8][8] = {};
    gemm_tile(g_xo + (size_t)m0 * DIMC, DIMC, pw    + (size_t)n0 * DIMC, DIMC, DIMC, acc, As, Bs, tid);
    gemm_tile(g_dv + (size_t)m0 * LDIM, LDIM, g_W2t + (size_t)n0 * LDIM, LDIM, LDIM, acc, As, Bs, tid);

    const int tm = tid >> 4, tn = tid & 15;
    float bb[8];
    #pragma unroll
    for (int j = 0; j < 8; j++)
        bb[j] = g_b2[n0 + ((j < 4) ? (tn * 4 + j) : (64 + tn * 4 + (j - 4)))];

    #pragma unroll
    for (int i = 0; i < 8; i++) {
        int m = m0 + ((i < 4) ? (tm * 4 + i) : (64 + tm * 4 + (i - 4)));
        float4 v0 = make_float4(acc[i][0] + bb[0], acc[i][1] + bb[1],
                                acc[i][2] + bb[2], acc[i][3] + bb[3]);
        float4 v1 = make_float4(acc[i][4] + bb[4], acc[i][5] + bb[5],
                                acc[i][6] + bb[6], acc[i][7] + bb[7]);
        *(float4*)(out + (size_t)m * DIMC + n0 + tn * 4)      = v0;
        *(float4*)(out + (size_t)m * DIMC + n0 + 64 + tn * 4) = v1;
    }
}

// ---------------- launch ----------------
extern "C" void kernel_launch(void* const* d_in, const int* in_sizes, int n_in,
                              void* d_out, int out_size) {
    const float* x       = (const float*)d_in[0];
    const float* mask    = (const float*)d_in[1];
    const int*   rpi     = (const int*)  d_in[2];
    const float* table   = (const float*)d_in[3];
    const float* qkv_w   = (const float*)d_in[4];
    const float* qkv_b   = (const float*)d_in[5];
    const float* proj_w  = (const float*)d_in[6];
    const float* proj_b  = (const float*)d_in[7];
    const float* qlw     = (const float*)d_in[8];
    const float* klw     = (const float*)d_in[9];
    const float* vlw     = (const float*)d_in[10];
    const float* lam1p   = (const float*)d_in[11];
    const float* lam2p   = (const float*)d_in[12];
    const float* dpw     = (const float*)d_in[13];
    const float* dpb     = (const float*)d_in[14];
    const float* gamma_p = (const float*)d_in[15];
    float* out = (float*)d_out;

    prep_bias_kernel<<<(NHEADS * NNSQ + 255) / 256, 256>>>(rpi, table);
    prep_w2_kernel<<<DIMC, LDIM>>>(dpw, proj_w, gamma_p);
    prep_b2_kernel<<<2, 256>>>(dpb, proj_w, proj_b, gamma_p);

    gemm1_kernel<<<dim3(15, MROWS / 128), 256>>>(x, qkv_w, qkv_b, qlw, klw, vlw);
    attn_kernel<<<NB * NHEADS, 256>>>(mask, lam1p, lam2p);
    gemm3_kernel<<<dim3(4, MROWS / 128), 256>>>(out, proj_w);
}

// round 4
// speedup vs baseline: 1.6267x; 1.6267x over previous
#include <cuda_runtime.h>
#include <math.h>
#include <stdint.h>

// ---------------- problem constants ----------------
#define DIMC   512
#define NHEADS 16
#define HD     32
#define LHD    8
#define LDIM   128
#define NTOK   49
#define NB     2048
#define NWIN   64
#define MROWS  (NB*NTOK)        // 100352
#define NNSQ   (NTOK*NTOK)      // 2401
#define SMLD   20               // padded k-stride in smem (16 -> 20, conflict-free frag LDS)

// ---------------- device scratch (no allocations allowed) ----------------
__device__ float g_q [NB*NHEADS*NTOK*HD];
__device__ float g_k [NB*NHEADS*NTOK*HD];
__device__ float g_v [NB*NHEADS*NTOK*HD];
__device__ float g_ql[NB*NHEADS*NTOK*LHD];
__device__ float g_kl[NB*NHEADS*NTOK*LHD];
__device__ float g_vl[NB*NHEADS*NTOK*LHD];
__device__ float g_xo[(size_t)MROWS*DIMC];
__device__ float g_dv[(size_t)MROWS*LDIM];
__device__ float g_relbias[NHEADS*NNSQ];
__device__ float g_W2t[DIMC*LDIM];
__device__ float g_b2 [DIMC];

// ---------------- prep kernels ----------------
__global__ void prep_bias_kernel(const int* __restrict__ rpi,
                                 const float* __restrict__ table) {
    int idx = blockIdx.x * 256 + threadIdx.x;
    if (idx < NHEADS * NNSQ) {
        int h = idx / NNSQ, ij = idx % NNSQ;
        g_relbias[idx] = table[rpi[ij] * NHEADS + h];
    }
}

// W2t[o][l] = gamma * sum_c dpw[c][l] * pw[o][c]
__global__ void prep_w2_kernel(const float* __restrict__ dpw,
                               const float* __restrict__ pw,
                               const float* __restrict__ gamma_p) {
    int o = blockIdx.x;        // 512
    int l = threadIdx.x;       // 128
    float s = 0.f;
    for (int c = 0; c < DIMC; c++)
        s += dpw[c * LDIM + l] * pw[o * DIMC + c];
    g_W2t[o * LDIM + l] = (*gamma_p) * s;
}

// b2[o] = pb[o] + gamma * sum_c dpb[c] * pw[o][c]
__global__ void prep_b2_kernel(const float* __restrict__ dpb,
                               const float* __restrict__ pw,
                               const float* __restrict__ pb,
                               const float* __restrict__ gamma_p) {
    int o = blockIdx.x * 256 + threadIdx.x;
    if (o < DIMC) {
        float s = 0.f;
        for (int c = 0; c < DIMC; c++) s += dpb[c] * pw[o * DIMC + c];
        g_b2[o] = pb[o] + (*gamma_p) * s;
    }
}

// ---------------- tf32 helpers ----------------
__device__ __forceinline__ uint32_t f2tf32(float x) {
    uint32_t r;
    asm("cvt.rna.tf32.f32 %0, %1;" : "=r"(r) : "f"(x));
    return r;
}

__device__ __forceinline__ void mma_tf32(float c[4],
                                         const uint32_t a[4],
                                         const uint32_t b[2]) {
    asm volatile(
        "mma.sync.aligned.m16n8k8.row.col.f32.tf32.tf32.f32 "
        "{%0,%1,%2,%3}, {%4,%5,%6,%7}, {%8,%9}, {%0,%1,%2,%3};"
        : "+f"(c[0]), "+f"(c[1]), "+f"(c[2]), "+f"(c[3])
        : "r"(a[0]), "r"(a[1]), "r"(a[2]), "r"(a[3]),
          "r"(b[0]), "r"(b[1]));
}

// ---------------- tf32 mma GEMM tile core ----------------
// acc[4][4][4] += A[128 x K] * B[128 x K]^T  (both row-major, K % 16 == 0)
// 8 warps (256 threads), warp tile 64x32, double-buffered smem, 1 sync/iter.
__device__ __forceinline__ void mma_tile(const float* __restrict__ A, int lda,
                                         const float* __restrict__ B, int ldb,
                                         int K, float (&acc)[4][4][4],
                                         uint32_t* As, uint32_t* Bs) {
    const int tid = threadIdx.x;
    const int lane = tid & 31, warp = tid >> 5;
    const int warpM = (warp >> 2) * 64, warpN = (warp & 3) * 32;
    const int row = lane >> 2, tg = lane & 3;
    const int ldrow = tid >> 1, ldk = (tid & 1) * 8;

    const float* Ap = A + (size_t)ldrow * lda + ldk;
    const float* Bp = B + (size_t)ldrow * ldb + ldk;
    uint32_t* asd = As + ldrow * SMLD + ldk;
    uint32_t* bsd = Bs + ldrow * SMLD + ldk;

    __syncthreads();   // protect against previous use of the buffers
    // prologue: stage k-tile 0 into buffer 0
    {
        float4 a0 = *(const float4*)(Ap);
        float4 a1 = *(const float4*)(Ap + 4);
        float4 b0 = *(const float4*)(Bp);
        float4 b1 = *(const float4*)(Bp + 4);
        ((uint4*)asd)[0] = make_uint4(f2tf32(a0.x), f2tf32(a0.y), f2tf32(a0.z), f2tf32(a0.w));
        ((uint4*)asd)[1] = make_uint4(f2tf32(a1.x), f2tf32(a1.y), f2tf32(a1.z), f2tf32(a1.w));
        ((uint4*)bsd)[0] = make_uint4(f2tf32(b0.x), f2tf32(b0.y), f2tf32(b0.z), f2tf32(b0.w));
        ((uint4*)bsd)[1] = make_uint4(f2tf32(b1.x), f2tf32(b1.y), f2tf32(b1.z), f2tf32(b1.w));
    }
    __syncthreads();

    const int nk = K >> 4;
    for (int kt = 0; kt < nk; kt++) {
        float4 a0, a1, b0, b1;
        const bool more = (kt + 1 < nk);
        if (more) {
            const float* An = Ap + (kt + 1) * 16;
            const float* Bn = Bp + (kt + 1) * 16;
            a0 = *(const float4*)(An);
            a1 = *(const float4*)(An + 4);
            b0 = *(const float4*)(Bn);
            b1 = *(const float4*)(Bn + 4);
        }

        const uint32_t* Ac = As + (kt & 1) * (128 * SMLD);
        const uint32_t* Bc = Bs + (kt & 1) * (128 * SMLD);

        #pragma unroll
        for (int kb = 0; kb < 16; kb += 8) {
            uint32_t af[4][4], bf[4][2];
            #pragma unroll
            for (int mt = 0; mt < 4; mt++) {
                const uint32_t* p = Ac + (warpM + mt * 16 + row) * SMLD + kb + tg;
                af[mt][0] = p[0];
                af[mt][1] = p[8 * SMLD];
                af[mt][2] = p[4];
                af[mt][3] = p[8 * SMLD + 4];
            }
            #pragma unroll
            for (int nt = 0; nt < 4; nt++) {
                const uint32_t* p = Bc + (warpN + nt * 8 + row) * SMLD + kb + tg;
                bf[nt][0] = p[0];
                bf[nt][1] = p[4];
            }
            #pragma unroll
            for (int mt = 0; mt < 4; mt++)
                #pragma unroll
                for (int nt = 0; nt < 4; nt++)
                    mma_tf32(acc[mt][nt], af[mt], bf[nt]);
        }

        if (more) {
            uint32_t* an = asd + ((kt + 1) & 1) * (128 * SMLD);
            uint32_t* bn = bsd + ((kt + 1) & 1) * (128 * SMLD);
            ((uint4*)an)[0] = make_uint4(f2tf32(a0.x), f2tf32(a0.y), f2tf32(a0.z), f2tf32(a0.w));
            ((uint4*)an)[1] = make_uint4(f2tf32(a1.x), f2tf32(a1.y), f2tf32(a1.z), f2tf32(a1.w));
            ((uint4*)bn)[0] = make_uint4(f2tf32(b0.x), f2tf32(b0.y), f2tf32(b0.z), f2tf32(b0.w));
            ((uint4*)bn)[1] = make_uint4(f2tf32(b1.x), f2tf32(b1.y), f2tf32(b1.z), f2tf32(b1.w));
            __syncthreads();
        }
    }
}

// ---------------- GEMM1: fused qkv + lite projections, scatter epilogue ----------------
__global__ __launch_bounds__(256, 2)
void gemm1_kernel(const float* __restrict__ x,
                  const float* __restrict__ qkv_w, const float* __restrict__ qkv_b,
                  const float* __restrict__ qlw, const float* __restrict__ klw,
                  const float* __restrict__ vlw) {
    __shared__ uint32_t As[2 * 128 * SMLD];
    __shared__ uint32_t Bs[2 * 128 * SMLD];
    const int m0 = blockIdx.y * 128;
    const int n0 = blockIdx.x * 128;

    const float* Bp;
    if (n0 < 1536)       Bp = qkv_w + (size_t)n0 * DIMC;
    else if (n0 == 1536) Bp = qlw;
    else if (n0 == 1664) Bp = klw;
    else                 Bp = vlw;

    float acc[4][4][4] = {};
    mma_tile(x + (size_t)m0 * DIMC, DIMC, Bp, DIMC, DIMC, acc, As, Bs);

    const int lane = threadIdx.x & 31, warp = threadIdx.x >> 5;
    const int warpM = (warp >> 2) * 64, warpN = (warp & 3) * 32;
    const int row = lane >> 2, tg2 = (lane & 3) * 2;
    const bool is_qkv = (n0 < 1536);

    #pragma unroll
    for (int mt = 0; mt < 4; mt++) {
        #pragma unroll
        for (int half = 0; half < 2; half++) {
            int m = m0 + warpM + mt * 16 + row + half * 8;
            int b = m / NTOK, n = m - b * NTOK;
            #pragma unroll
            for (int nt = 0; nt < 4; nt++) {
                int c = n0 + warpN + nt * 8 + tg2;
                float v0 = acc[mt][nt][half * 2 + 0];
                float v1 = acc[mt][nt][half * 2 + 1];
                if (is_qkv) {
                    v0 += qkv_b[c];
                    v1 += qkv_b[c + 1];
                    int jj = c >> 9, hh = (c >> 5) & 15, d = c & 31;
                    float* dst = (jj == 0) ? g_q : ((jj == 1) ? g_k : g_v);
                    *(float2*)&dst[((size_t)(b * NHEADS + hh) * NTOK + n) * HD + d] =
                        make_float2(v0, v1);
                } else {
                    int cc = c - 1536;
                    int jj = cc >> 7, hh = (cc >> 3) & 15, d = cc & 7;
                    float* dst = (jj == 0) ? g_ql : ((jj == 1) ? g_kl : g_vl);
                    *(float2*)&dst[((size_t)(b * NHEADS + hh) * NTOK + n) * LHD + d] =
                        make_float2(v0, v1);
                }
            }
        }
    }
}

// ---------------- fused dual attention, one block per (b,h) ----------------
__global__ __launch_bounds__(256)
void attn_kernel(const float* __restrict__ mask,
                 const float* __restrict__ lam1p,
                 const float* __restrict__ lam2p) {
    __shared__ float sq[NTOK * HD];
    __shared__ float skT[HD * NTOK];     // transposed: [d][j]
    __shared__ float sv[NTOK * HD];
    __shared__ float sql[NTOK * LHD];
    __shared__ float sklT[LHD * NTOK];   // transposed
    __shared__ float svl[NTOK * LHD];
    __shared__ float sp[NNSQ];
    __shared__ float spl[NNSQ];

    const int bid = blockIdx.x;
    const int b = bid >> 4, h = bid & 15;
    const int win = b & (NWIN - 1);
    const int tid = threadIdx.x;
    const size_t base  = (size_t)bid * (NTOK * HD);
    const size_t basel = (size_t)bid * (NTOK * LHD);

    for (int idx = tid; idx < NTOK * HD; idx += 256) {
        sq[idx] = g_q[base + idx];
        int j = idx >> 5, d = idx & 31;
        skT[d * NTOK + j] = g_k[base + idx];
        sv[idx] = g_v[base + idx];
    }
    for (int idx = tid; idx < NTOK * LHD; idx += 256) {
        sql[idx] = g_ql[basel + idx];
        int j = idx >> 3, d = idx & 7;
        sklT[d * NTOK + j] = g_kl[basel + idx];
        svl[idx] = g_vl[basel + idx];
    }
    __syncthreads();

    const float scale   = 0.17677669529663687f;  // 32^-0.5
    const float scale_l = 0.35355339059327373f;  // 8^-0.5
    const float* bias_h = g_relbias + h * NNSQ;
    const float* mask_w = mask + win * NNSQ;

    for (int idx = tid; idx < NNSQ; idx += 256) {
        int i = idx / NTOK, j = idx - i * NTOK;
        float bm = bias_h[idx] + mask_w[idx];
        float dot = 0.f;
        #pragma unroll
        for (int d = 0; d < HD; d++) dot += sq[i * HD + d] * skT[d * NTOK + j];
        float dotl = 0.f;
        #pragma unroll
        for (int d = 0; d < LHD; d++) dotl += sql[i * LHD + d] * sklT[d * NTOK + j];
        sp[idx]  = dot  * scale   + bm;
        spl[idx] = dotl * scale_l + bm;
    }
    __syncthreads();

    if (tid < 2 * NTOK) {
        float* row = ((tid < NTOK) ? sp : spl) + ((tid < NTOK) ? tid : tid - NTOK) * NTOK;
        float mx = row[0];
        for (int j = 1; j < NTOK; j++) mx = fmaxf(mx, row[j]);
        float s = 0.f;
        for (int j = 0; j < NTOK; j++) { float e = expf(row[j] - mx); row[j] = e; s += e; }
        float inv = 1.f / s;
        for (int j = 0; j < NTOK; j++) row[j] *= inv;
    }
    __syncthreads();

    const float lam1 = 1.f / (1.f + expf(-*lam1p));
    const float lam2 = 1.f / (1.f + expf(-*lam2p));

    for (int o = tid; o < NTOK * HD; o += 256) {
        int i = o >> 5, d = o & 31;
        float s = 0.f;
        #pragma unroll
        for (int j = 0; j < NTOK; j++) s += sp[i * NTOK + j] * sv[j * HD + d];
        g_xo[((size_t)(b * NTOK + i)) * DIMC + h * HD + d] = s;
    }
    for (int o = tid; o < NTOK * LHD; o += 256) {
        int i = o >> 3, d = o & 7;
        float s = 0.f;
        #pragma unroll
        for (int j = 0; j < NTOK; j++)
            s += (lam1 * spl[i * NTOK + j] - lam2 * sp[i * NTOK + j]) * svl[j * LHD + d];
        g_dv[((size_t)(b * NTOK + i)) * LDIM + h * LHD + d] = s;
    }
}

// ---------------- GEMM3: out = xo@Wp^T + dv@W2t^T + b2 ----------------
__global__ __launch_bounds__(256, 2)
void gemm3_kernel(float* __restrict__ out, const float* __restrict__ pw) {
    __shared__ uint32_t As[2 * 128 * SMLD];
    __shared__ uint32_t Bs[2 * 128 * SMLD];
    const int m0 = blockIdx.y * 128;
    const int n0 = blockIdx.x * 128;

    float acc[4][4][4] = {};
    mma_tile(g_xo + (size_t)m0 * DIMC, DIMC, pw + (size_t)n0 * DIMC, DIMC, DIMC,
             acc, As, Bs);
    mma_tile(g_dv + (size_t)m0 * LDIM, LDIM, g_W2t + (size_t)n0 * LDIM, LDIM, LDIM,
             acc, As, Bs);

    const int lane = threadIdx.x & 31, warp = threadIdx.x >> 5;
    const int warpM = (warp >> 2) * 64, warpN = (warp & 3) * 32;
    const int row = lane >> 2, tg2 = (lane & 3) * 2;

    #pragma unroll
    for (int nt = 0; nt < 4; nt++) {
        int c = n0 + warpN + nt * 8 + tg2;
        float b0 = g_b2[c], b1 = g_b2[c + 1];
        #pragma unroll
        for (int mt = 0; mt < 4; mt++) {
            #pragma unroll
            for (int half = 0; half < 2; half++) {
                int m = m0 + warpM + mt * 16 + row + half * 8;
                *(float2*)&out[(size_t)m * DIMC + c] =
                    make_float2(acc[mt][nt][half * 2 + 0] + b0,
                                acc[mt][nt][half * 2 + 1] + b1);
            }
        }
    }
}

// ---------------- launch ----------------
extern "C" void kernel_launch(void* const* d_in, const int* in_sizes, int n_in,
                              void* d_out, int out_size) {
    const float* x       = (const float*)d_in[0];
    const float* mask    = (const float*)d_in[1];
    const int*   rpi     = (const int*)  d_in[2];
    const float* table   = (const float*)d_in[3];
    const float* qkv_w   = (const float*)d_in[4];
    const float* qkv_b   = (const float*)d_in[5];
    const float* proj_w  = (const float*)d_in[6];
    const float* proj_b  = (const float*)d_in[7];
    const float* qlw     = (const float*)d_in[8];
    const float* klw     = (const float*)d_in[9];
    const float* vlw     = (const float*)d_in[10];
    const float* lam1p   = (const float*)d_in[11];
    const float* lam2p   = (const float*)d_in[12];
    const float* dpw     = (const float*)d_in[13];
    const float* dpb     = (const float*)d_in[14];
    const float* gamma_p = (const float*)d_in[15];
    float* out = (float*)d_out;

    prep_bias_kernel<<<(NHEADS * NNSQ + 255) / 256, 256>>>(rpi, table);
    prep_w2_kernel<<<DIMC, LDIM>>>(dpw, proj_w, gamma_p);
    prep_b2_kernel<<<2, 256>>>(dpb, proj_w, proj_b, gamma_p);

    gemm1_kernel<<<dim3(15, MROWS / 128), 256>>>(x, qkv_w, qkv_b, qlw, klw, vlw);
    attn_kernel<<<NB * NHEADS, 256>>>(mask, lam1p, lam2p);
    gemm3_kernel<<<dim3(4, MROWS / 128), 256>>>(out, proj_w);
}

// round 7
// speedup vs baseline: 1.6568x; 1.0185x over previous
#include <cuda_runtime.h>
#include <cuda_fp16.h>
#include <math.h>
#include <stdint.h>

// ---------------- problem constants ----------------
#define DIMC   512
#define NHEADS 16
#define HD     32
#define LHD    8
#define LDIM   128
#define NTOK   49
#define NB     2048
#define NWIN   64
#define MROWS  (NB*NTOK)        // 100352
#define NNSQ   (NTOK*NTOK)      // 2401
#define STAGE_U32 1024          // 4KB per stage per operand ([2 kb][128 rows][16B])

// ---------------- device scratch (no allocations allowed) ----------------
__device__ float g_q [NB*NHEADS*NTOK*HD];
__device__ float g_k [NB*NHEADS*NTOK*HD];
__device__ float g_v [NB*NHEADS*NTOK*HD];
__device__ float g_ql[NB*NHEADS*NTOK*LHD];
__device__ float g_kl[NB*NHEADS*NTOK*LHD];
__device__ float g_vl[NB*NHEADS*NTOK*LHD];
__device__ float g_xo[(size_t)MROWS*DIMC];
__device__ float g_dv[(size_t)MROWS*LDIM];
__device__ float g_relbias[NHEADS*NNSQ];
__device__ float g_W2t[DIMC*LDIM];
__device__ float g_b2 [DIMC];

// ---------------- prep kernels ----------------
__global__ void prep_bias_kernel(const int* __restrict__ rpi,
                                 const float* __restrict__ table) {
    int idx = blockIdx.x * 256 + threadIdx.x;
    if (idx < NHEADS * NNSQ) {
        int h = idx / NNSQ, ij = idx % NNSQ;
        g_relbias[idx] = table[rpi[ij] * NHEADS + h];
    }
}

__global__ void prep_w2_kernel(const float* __restrict__ dpw,
                               const float* __restrict__ pw,
                               const float* __restrict__ gamma_p) {
    int o = blockIdx.x;        // 512
    int l = threadIdx.x;       // 128
    float s = 0.f;
    for (int c = 0; c < DIMC; c++)
        s += dpw[c * LDIM + l] * pw[o * DIMC + c];
    g_W2t[o * LDIM + l] = (*gamma_p) * s;
}

__global__ void prep_b2_kernel(const float* __restrict__ dpb,
                               const float* __restrict__ pw,
                               const float* __restrict__ pb,
                               const float* __restrict__ gamma_p) {
    int o = blockIdx.x * 256 + threadIdx.x;
    if (o < DIMC) {
        float s = 0.f;
        for (int c = 0; c < DIMC; c++) s += dpb[c] * pw[o * DIMC + c];
        g_b2[o] = pb[o] + (*gamma_p) * s;
    }
}

// ---------------- f16 helpers ----------------
__device__ __forceinline__ uint32_t pack2(float lo, float hi) {
    __half2 h = __floats2half2_rn(lo, hi);
    return *(uint32_t*)&h;
}

__device__ __forceinline__ void mma_f16(float c[4], const uint32_t a[4],
                                        uint32_t b0, uint32_t b1) {
    asm volatile(
        "mma.sync.aligned.m16n8k16.row.col.f32.f16.f16.f32 "
        "{%0,%1,%2,%3}, {%4,%5,%6,%7}, {%8,%9}, {%0,%1,%2,%3};"
        : "+f"(c[0]), "+f"(c[1]), "+f"(c[2]), "+f"(c[3])
        : "r"(a[0]), "r"(a[1]), "r"(a[2]), "r"(a[3]), "r"(b0), "r"(b1));
}

__device__ __forceinline__ void ldsm_x4(uint32_t r[4], uint32_t saddr) {
    asm volatile("ldmatrix.sync.aligned.m8n8.x4.shared.b16 {%0,%1,%2,%3}, [%4];"
        : "=r"(r[0]), "=r"(r[1]), "=r"(r[2]), "=r"(r[3]) : "r"(saddr));
}

// ---------------- f16 mma GEMM tile core ----------------
// acc[4][4][4] += A[128 x K] * B[128 x K]^T (row-major), converted to f16 in smem.
// 8 warps, warp tile 64x32, k16 stages, double-buffered, conflict-free ldmatrix.
__device__ __forceinline__ void mma_tile_f16(
        const float* __restrict__ A, int lda,
        const float* __restrict__ B, int ldb,
        int K, float (&acc)[4][4][4],
        uint32_t* As, uint32_t* Bs) {
    const int tid = threadIdx.x;
    const int lane = tid & 31, warp = tid >> 5;
    const int warpM = (warp >> 2) * 64, warpN = (warp & 3) * 32;

    // producer mapping: 128 rows x 2 k-halves
    const int prow = tid & 127, pkh = tid >> 7;
    const float* Ap = A + (size_t)prow * lda + pkh * 8;
    const float* Bp = B + (size_t)prow * ldb + pkh * 8;
    uint32_t* asd = As + pkh * 512 + prow * 4;   // u32 units; 16B per row
    uint32_t* bsd = Bs + pkh * 512 + prow * 4;

    // ldmatrix per-thread byte offsets within a stage
    const int rowA = (lane & 7) + ((lane >> 3) & 1) * 8;
    const uint32_t aoff = (uint32_t)(lane >> 4) * 2048u + (uint32_t)(warpM + rowA) * 16u;
    const int rowB = (lane & 7) + (lane >> 4) * 8;
    const uint32_t boff = (uint32_t)((lane >> 3) & 1) * 2048u + (uint32_t)(warpN + rowB) * 16u;
    const uint32_t aBase = (uint32_t)__cvta_generic_to_shared(As) + aoff;
    const uint32_t bBase = (uint32_t)__cvta_generic_to_shared(Bs) + boff;

    __syncthreads();   // buffers may be in use by a previous call
    {   // prologue: stage 0 -> buffer 0
        float4 a0 = *(const float4*)Ap, a1 = *(const float4*)(Ap + 4);
        float4 b0 = *(const float4*)Bp, b1 = *(const float4*)(Bp + 4);
        ((uint4*)asd)[0] = make_uint4(pack2(a0.x,a0.y), pack2(a0.z,a0.w),
                                      pack2(a1.x,a1.y), pack2(a1.z,a1.w));
        ((uint4*)bsd)[0] = make_uint4(pack2(b0.x,b0.y), pack2(b0.z,b0.w),
                                      pack2(b1.x,b1.y), pack2(b1.z,b1.w));
    }
    __syncthreads();

    const int nk = K >> 4;
    for (int kt = 0; kt < nk; kt++) {
        uint4 an, bn;
        const bool more = (kt + 1 < nk);
        if (more) {
            float4 a0 = *(const float4*)(Ap + (kt + 1) * 16);
            float4 a1 = *(const float4*)(Ap + (kt + 1) * 16 + 4);
            float4 b0 = *(const float4*)(Bp + (kt + 1) * 16);
            float4 b1 = *(const float4*)(Bp + (kt + 1) * 16 + 4);
            an = make_uint4(pack2(a0.x,a0.y), pack2(a0.z,a0.w),
                            pack2(a1.x,a1.y), pack2(a1.z,a1.w));
            bn = make_uint4(pack2(b0.x,b0.y), pack2(b0.z,b0.w),
                            pack2(b1.x,b1.y), pack2(b1.z,b1.w));
        }

        const uint32_t abuf = aBase + (uint32_t)(kt & 1) * 4096u;
        const uint32_t bbuf = bBase + (uint32_t)(kt & 1) * 4096u;
        uint32_t af[4][4], bf[2][4];
        #pragma unroll
        for (int mt = 0; mt < 4; mt++) ldsm_x4(af[mt], abuf + mt * 256u);
        #pragma unroll
        for (int p = 0; p < 2; p++)   ldsm_x4(bf[p], bbuf + p * 256u);

        #pragma unroll
        for (int mt = 0; mt < 4; mt++)
            #pragma unroll
            for (int nt = 0; nt < 4; nt++)
                mma_f16(acc[mt][nt], af[mt],
                        bf[nt >> 1][(nt & 1) * 2], bf[nt >> 1][(nt & 1) * 2 + 1]);

        if (more) {
            ((uint4*)(asd + ((kt + 1) & 1) * STAGE_U32))[0] = an;
            ((uint4*)(bsd + ((kt + 1) & 1) * STAGE_U32))[0] = bn;
            __syncthreads();
        }
    }
}

// ---------------- GEMM1: fused qkv + lite projections, scatter epilogue ----------------
__global__ __launch_bounds__(256, 2)
void gemm1_kernel(const float* __restrict__ x,
                  const float* __restrict__ qkv_w, const float* __restrict__ qkv_b,
                  const float* __restrict__ qlw, const float* __restrict__ klw,
                  const float* __restrict__ vlw) {
    __shared__ __align__(16) uint32_t As[2 * STAGE_U32];
    __shared__ __align__(16) uint32_t Bs[2 * STAGE_U32];
    const int m0 = blockIdx.y * 128;
    const int n0 = blockIdx.x * 128;

    const float* Bp;
    if (n0 < 1536)       Bp = qkv_w + (size_t)n0 * DIMC;
    else if (n0 == 1536) Bp = qlw;
    else if (n0 == 1664) Bp = klw;
    else                 Bp = vlw;

    float acc[4][4][4] = {};
    mma_tile_f16(x + (size_t)m0 * DIMC, DIMC, Bp, DIMC, DIMC, acc, As, Bs);

    const int lane = threadIdx.x & 31, warp = threadIdx.x >> 5;
    const int warpM = (warp >> 2) * 64, warpN = (warp & 3) * 32;
    const int row = lane >> 2, tg2 = (lane & 3) * 2;
    const bool is_qkv = (n0 < 1536);

    #pragma unroll
    for (int mt = 0; mt < 4; mt++) {
        #pragma unroll
        for (int half = 0; half < 2; half++) {
            int m = m0 + warpM + mt * 16 + row + half * 8;
            int b = m / NTOK, n = m - b * NTOK;
            #pragma unroll
            for (int nt = 0; nt < 4; nt++) {
                int c = n0 + warpN + nt * 8 + tg2;
                float v0 = acc[mt][nt][half * 2 + 0];
                float v1 = acc[mt][nt][half * 2 + 1];
                if (is_qkv) {
                    v0 += qkv_b[c];
                    v1 += qkv_b[c + 1];
                    int jj = c >> 9, hh = (c >> 5) & 15, d = c & 31;
                    float* dst = (jj == 0) ? g_q : ((jj == 1) ? g_k : g_v);
                    *(float2*)&dst[((size_t)(b * NHEADS + hh) * NTOK + n) * HD + d] =
                        make_float2(v0, v1);
                } else {
                    int cc = c - 1536;
                    int jj = cc >> 7, hh = (cc >> 3) & 15, d = cc & 7;
                    float* dst = (jj == 0) ? g_ql : ((jj == 1) ? g_kl : g_vl);
                    *(float2*)&dst[((size_t)(b * NHEADS + hh) * NTOK + n) * LHD + d] =
                        make_float2(v0, v1);
                }
            }
        }
    }
}

// ---------------- fused dual attention, one block per (b,h) ----------------
__global__ __launch_bounds__(256)
void attn_kernel(const float* __restrict__ mask,
                 const float* __restrict__ lam1p,
                 const float* __restrict__ lam2p) {
    __shared__ float sq[NTOK * HD];
    __shared__ float skT[HD * NTOK];     // transposed: [d][j]
    __shared__ float sv[NTOK * HD];
    __shared__ float sql[NTOK * LHD];
    __shared__ float sklT[LHD * NTOK];   // transposed
    __shared__ float svl[NTOK * LHD];
    __shared__ float sp[NNSQ];
    __shared__ float spl[NNSQ];

    const int bid = blockIdx.x;
    const int b = bid >> 4, h = bid & 15;
    const int win = b & (NWIN - 1);
    const int tid = threadIdx.x;
    const size_t base  = (size_t)bid * (NTOK * HD);
    const size_t basel = (size_t)bid * (NTOK * LHD);

    for (int idx = tid; idx < NTOK * HD; idx += 256) {
        sq[idx] = g_q[base + idx];
        int j = idx >> 5, d = idx & 31;
        skT[d * NTOK + j] = g_k[base + idx];
        sv[idx] = g_v[base + idx];
    }
    for (int idx = tid; idx < NTOK * LHD; idx += 256) {
        sql[idx] = g_ql[basel + idx];
        int j = idx >> 3, d = idx & 7;
        sklT[d * NTOK + j] = g_kl[basel + idx];
        svl[idx] = g_vl[basel + idx];
    }
    __syncthreads();

    const float scale   = 0.17677669529663687f;  // 32^-0.5
    const float scale_l = 0.35355339059327373f;  // 8^-0.5
    const float* bias_h = g_relbias + h * NNSQ;
    const float* mask_w = mask + win * NNSQ;

    for (int idx = tid; idx < NNSQ; idx += 256) {
        int i = idx / NTOK, j = idx - i * NTOK;
        float bm = bias_h[idx] + mask_w[idx];
        float dot = 0.f;
        #pragma unroll
        for (int d = 0; d < HD; d++) dot += sq[i * HD + d] * skT[d * NTOK + j];
        float dotl = 0.f;
        #pragma unroll
        for (int d = 0; d < LHD; d++) dotl += sql[i * LHD + d] * sklT[d * NTOK + j];
        sp[idx]  = dot  * scale   + bm;
        spl[idx] = dotl * scale_l + bm;
    }
    __syncthreads();

    if (tid < 2 * NTOK) {
        float* row = ((tid < NTOK) ? sp : spl) + ((tid < NTOK) ? tid : tid - NTOK) * NTOK;
        float mx = row[0];
        for (int j = 1; j < NTOK; j++) mx = fmaxf(mx, row[j]);
        float s = 0.f;
        for (int j = 0; j < NTOK; j++) { float e = expf(row[j] - mx); row[j] = e; s += e; }
        float inv = 1.f / s;
        for (int j = 0; j < NTOK; j++) row[j] *= inv;
    }
    __syncthreads();

    const float lam1 = 1.f / (1.f + expf(-*lam1p));
    const float lam2 = 1.f / (1.f + expf(-*lam2p));

    for (int o = tid; o < NTOK * HD; o += 256) {
        int i = o >> 5, d = o & 31;
        float s = 0.f;
        #pragma unroll
        for (int j = 0; j < NTOK; j++) s += sp[i * NTOK + j] * sv[j * HD + d];
        g_xo[((size_t)(b * NTOK + i)) * DIMC + h * HD + d] = s;
    }
    for (int o = tid; o < NTOK * LHD; o += 256) {
        int i = o >> 3, d = o & 7;
        float s = 0.f;
        #pragma unroll
        for (int j = 0; j < NTOK; j++)
            s += (lam1 * spl[i * NTOK + j] - lam2 * sp[i * NTOK + j]) * svl[j * LHD + d];
        g_dv[((size_t)(b * NTOK + i)) * LDIM + h * LHD + d] = s;
    }
}

// ---------------- GEMM3: out = xo@Wp^T + dv@W2t^T + b2 ----------------
__global__ __launch_bounds__(256, 2)
void gemm3_kernel(float* __restrict__ out, const float* __restrict__ pw) {
    __shared__ __align__(16) uint32_t As[2 * STAGE_U32];
    __shared__ __align__(16) uint32_t Bs[2 * STAGE_U32];
    const int m0 = blockIdx.y * 128;
    const int n0 = blockIdx.x * 128;

    float acc[4][4][4] = {};
    mma_tile_f16(g_xo + (size_t)m0 * DIMC, DIMC, pw + (size_t)n0 * DIMC, DIMC, DIMC,
                 acc, As, Bs);
    mma_tile_f16(g_dv + (size_t)m0 * LDIM, LDIM, g_W2t + (size_t)n0 * LDIM, LDIM, LDIM,
                 acc, As, Bs);

    const int lane = threadIdx.x & 31, warp = threadIdx.x >> 5;
    const int warpM = (warp >> 2) * 64, warpN = (warp & 3) * 32;
    const int row = lane >> 2, tg2 = (lane & 3) * 2;

    #pragma unroll
    for (int nt = 0; nt < 4; nt++) {
        int c = n0 + warpN + nt * 8 + tg2;
        float b0 = g_b2[c], b1 = g_b2[c + 1];
        #pragma unroll
        for (int mt = 0; mt < 4; mt++) {
            #pragma unroll
            for (int half = 0; half < 2; half++) {
                int m = m0 + warpM + mt * 16 + row + half * 8;
                *(float2*)&out[(size_t)m * DIMC + c] =
                    make_float2(acc[mt][nt][half * 2 + 0] + b0,
                                acc[mt][nt][half * 2 + 1] + b1);
            }
        }
    }
}

// ---------------- launch ----------------
extern "C" void kernel_launch(void* const* d_in, const int* in_sizes, int n_in,
                              void* d_out, int out_size) {
    const float* x       = (const float*)d_in[0];
    const float* mask    = (const float*)d_in[1];
    const int*   rpi     = (const int*)  d_in[2];
    const float* table   = (const float*)d_in[3];
    const float* qkv_w   = (const float*)d_in[4];
    const float* qkv_b   = (const float*)d_in[5];
    const float* proj_w  = (const float*)d_in[6];
    const float* proj_b  = (const float*)d_in[7];
    const float* qlw     = (const float*)d_in[8];
    const float* klw     = (const float*)d_in[9];
    const float* vlw     = (const float*)d_in[10];
    const float* lam1p   = (const float*)d_in[11];
    const float* lam2p   = (const float*)d_in[12];
    const float* dpw     = (const float*)d_in[13];
    const float* dpb     = (const float*)d_in[14];
    const float* gamma_p = (const float*)d_in[15];
    float* out = (float*)d_out;

    prep_bias_kernel<<<(NHEADS * NNSQ + 255) / 256, 256>>>(rpi, table);
    prep_w2_kernel<<<DIMC, LDIM>>>(dpw, proj_w, gamma_p);
    prep_b2_kernel<<<2, 256>>>(dpb, proj_w, proj_b, gamma_p);

    gemm1_kernel<<<dim3(15, MROWS / 128), 256>>>(x, qkv_w, qkv_b, qlw, klw, vlw);
    attn_kernel<<<NB * NHEADS, 256>>>(mask, lam1p, lam2p);
    gemm3_kernel<<<dim3(4, MROWS / 128), 256>>>(out, proj_w);
}

// round 9
// speedup vs baseline: 2.8233x; 1.7041x over previous
#include <cuda_runtime.h>
#include <cuda_fp16.h>
#include <math.h>
#include <stdint.h>

// ---------------- problem constants ----------------
#define DIMC   512
#define NHEADS 16
#define HD     32
#define LHD    8
#define LDIM   128
#define NTOK   49
#define NB     2048
#define NWIN   64
#define MROWS  (NB*NTOK)        // 100352
#define NNSQ   (NTOK*NTOK)      // 2401
#define NCOLS1 1920             // 1536 qkv + 384 lite
#define STAGEB 8192             // bytes per stage per operand (128 rows x 64B)

// ---------------- device scratch (no allocations allowed) ----------------
__device__ __align__(256) float  g_q [NB*NHEADS*NTOK*HD];
__device__ __align__(256) float  g_k [NB*NHEADS*NTOK*HD];
__device__ __align__(256) float  g_v [NB*NHEADS*NTOK*HD];
__device__ __align__(256) float  g_ql[NB*NHEADS*NTOK*LHD];
__device__ __align__(256) float  g_kl[NB*NHEADS*NTOK*LHD];
__device__ __align__(256) float  g_vl[NB*NHEADS*NTOK*LHD];
__device__ __align__(256) __half g_x16 [(size_t)MROWS*DIMC];
__device__ __align__(256) __half g_wB  [(size_t)NCOLS1*DIMC];   // packed qkv|ql|kl|vl
__device__ __align__(256) __half g_pw16[(size_t)DIMC*DIMC];
__device__ __align__(256) __half g_W2t16[DIMC*LDIM];
__device__ __align__(256) __half g_xo16[(size_t)MROWS*DIMC];
__device__ __align__(256) __half g_dv16[(size_t)MROWS*LDIM];
__device__ __align__(256) float  g_relbias[NHEADS*NNSQ];
__device__ __align__(256) float  g_b2 [DIMC];

// ---------------- conversion / prep kernels ----------------
__global__ void conv_x_kernel(const float* __restrict__ x) {
    size_t i4 = (size_t)blockIdx.x * 256 + threadIdx.x;     // float4 index
    float4 f = ((const float4*)x)[i4];
    __half2 h0 = __floats2half2_rn(f.x, f.y);
    __half2 h1 = __floats2half2_rn(f.z, f.w);
    ((uint2*)g_x16)[i4] = make_uint2(*(uint32_t*)&h0, *(uint32_t*)&h1);
}

__global__ void conv_wB_kernel(const float* __restrict__ qkv_w,
                               const float* __restrict__ qlw,
                               const float* __restrict__ klw,
                               const float* __restrict__ vlw) {
    int i4 = blockIdx.x * 256 + threadIdx.x;   // 0 .. 1920*512/4
    int row = i4 >> 7, col4 = i4 & 127;
    const float* src;
    if (row < 1536) src = qkv_w + (size_t)row * DIMC;
    else {
        int r2 = row - 1536, sel = r2 >> 7, lr = r2 & 127;
        src = ((sel == 0) ? qlw : (sel == 1) ? klw : vlw) + (size_t)lr * DIMC;
    }
    float4 f = ((const float4*)src)[col4];
    __half2 h0 = __floats2half2_rn(f.x, f.y);
    __half2 h1 = __floats2half2_rn(f.z, f.w);
    ((uint2*)g_wB)[i4] = make_uint2(*(uint32_t*)&h0, *(uint32_t*)&h1);
}

__global__ void conv_pw_kernel(const float* __restrict__ pw) {
    int i4 = blockIdx.x * 256 + threadIdx.x;
    float4 f = ((const float4*)pw)[i4];
    __half2 h0 = __floats2half2_rn(f.x, f.y);
    __half2 h1 = __floats2half2_rn(f.z, f.w);
    ((uint2*)g_pw16)[i4] = make_uint2(*(uint32_t*)&h0, *(uint32_t*)&h1);
}

__global__ void prep_bias_kernel(const int* __restrict__ rpi,
                                 const float* __restrict__ table) {
    int idx = blockIdx.x * 256 + threadIdx.x;
    if (idx < NHEADS * NNSQ) {
        int h = idx / NNSQ, ij = idx % NNSQ;
        g_relbias[idx] = table[rpi[ij] * NHEADS + h];
    }
}

__global__ void prep_w2_kernel(const float* __restrict__ dpw,
                               const float* __restrict__ pw,
                               const float* __restrict__ gamma_p) {
    int o = blockIdx.x, l = threadIdx.x;
    float s = 0.f;
    for (int c = 0; c < DIMC; c++)
        s += dpw[c * LDIM + l] * pw[o * DIMC + c];
    g_W2t16[o * LDIM + l] = __float2half_rn((*gamma_p) * s);
}

__global__ void prep_b2_kernel(const float* __restrict__ dpb,
                               const float* __restrict__ pw,
                               const float* __restrict__ pb,
                               const float* __restrict__ gamma_p) {
    int o = blockIdx.x * 256 + threadIdx.x;
    if (o < DIMC) {
        float s = 0.f;
        for (int c = 0; c < DIMC; c++) s += dpb[c] * pw[o * DIMC + c];
        g_b2[o] = pb[o] + (*gamma_p) * s;
    }
}

// ---------------- mma / cp.async helpers ----------------
__device__ __forceinline__ void mma_f16(float c[4], const uint32_t a[4],
                                        uint32_t b0, uint32_t b1) {
    asm volatile(
        "mma.sync.aligned.m16n8k16.row.col.f32.f16.f16.f32 "
        "{%0,%1,%2,%3}, {%4,%5,%6,%7}, {%8,%9}, {%0,%1,%2,%3};"
        : "+f"(c[0]), "+f"(c[1]), "+f"(c[2]), "+f"(c[3])
        : "r"(a[0]), "r"(a[1]), "r"(a[2]), "r"(a[3]), "r"(b0), "r"(b1));
}

__device__ __forceinline__ void ldsm_x4(uint32_t r[4], uint32_t saddr) {
    asm volatile("ldmatrix.sync.aligned.m8n8.x4.shared.b16 {%0,%1,%2,%3}, [%4];"
        : "=r"(r[0]), "=r"(r[1]), "=r"(r[2]), "=r"(r[3]) : "r"(saddr));
}

__device__ __forceinline__ void cpa16(uint32_t saddr, const void* g) {
    asm volatile("cp.async.cg.shared.global [%0], [%1], 16;" :: "r"(saddr), "l"(g));
}

// swizzled byte offset within an 8KB stage for (logical row r, k-octet kb)
__device__ __forceinline__ uint32_t swz(int r, int kb) {
    int s = r >> 1;
    int c = ((r & 1) << 2) | kb;
    return (uint32_t)((s << 7) + (((c ^ (s & 7)) << 4)));
}

// ---------------- cp.async fp16 mma GEMM tile core ----------------
// acc += A[128 x K] * B[128 x K]^T, A/B fp16 row-major in global (lda/ldb elems).
// 8 warps, warp tile 64x32. k32 stages, 4-stage cp.async ring, swizzled smem.
__device__ __forceinline__ void mma_tile_cp(
        const __half* __restrict__ Ag, int lda,
        const __half* __restrict__ Bg, int ldb,
        int nk, float (&acc)[4][4][4],
        uint32_t aSm, uint32_t bSm) {
    const int tid = threadIdx.x;
    const int lane = tid & 31, warp = tid >> 5;
    const int warpM = (warp >> 2) * 64, warpN = (warp & 3) * 32;

    // producer: unit u covers (row u>>2, k-octet u&3); thread owns u=tid and u=tid+256
    const int r0 = tid >> 2, kb0 = tid & 3;
    const __half* gA0 = Ag + (size_t)r0 * lda + kb0 * 8;
    const __half* gB0 = Bg + (size_t)r0 * ldb + kb0 * 8;
    const size_t a64 = (size_t)64 * lda, b64 = (size_t)64 * ldb;
    const uint32_t sA0 = aSm + swz(r0, kb0),      sA1 = aSm + swz(r0 + 64, kb0);
    const uint32_t sB0 = bSm + swz(r0, kb0),      sB1 = bSm + swz(r0 + 64, kb0);

    // ldmatrix per-lane offsets (within a stage)
    uint32_t offA[4][2], offB[2][2];
    {
        int rl = (lane & 7) + ((lane >> 3) & 1) * 8;
        int ka = lane >> 4;
        #pragma unroll
        for (int mt = 0; mt < 4; mt++)
            #pragma unroll
            for (int t = 0; t < 2; t++)
                offA[mt][t] = swz(warpM + mt * 16 + rl, 2 * t + ka);
        int rb = (lane & 7) + ((lane >> 4) & 1) * 8;
        int kbb = (lane >> 3) & 1;
        #pragma unroll
        for (int p = 0; p < 2; p++)
            #pragma unroll
            for (int t = 0; t < 2; t++)
                offB[p][t] = swz(warpN + p * 16 + rb, 2 * t + kbb);
    }

#define ISSUE_STAGE(S) do {                                           \
        int _s = (S);                                                 \
        if (_s < nk) {                                                \
            const __half* _ga = gA0 + _s * 32;                        \
            const __half* _gb = gB0 + _s * 32;                        \
            uint32_t _so = (uint32_t)(_s & 3) * STAGEB;               \
            cpa16(sA0 + _so, _ga); cpa16(sA1 + _so, _ga + a64);       \
            cpa16(sB0 + _so, _gb); cpa16(sB1 + _so, _gb + b64);       \
        }                                                             \
        asm volatile("cp.async.commit_group;");                       \
    } while (0)

    __syncthreads();   // smem may be in use by a previous call
    ISSUE_STAGE(0);
    ISSUE_STAGE(1);
    ISSUE_STAGE(2);

    for (int kt = 0; kt < nk; kt++) {
        asm volatile("cp.async.wait_group 2;");
        __syncthreads();
        ISSUE_STAGE(kt + 3);

        const uint32_t as_ = aSm + (uint32_t)(kt & 3) * STAGEB;
        const uint32_t bs_ = bSm + (uint32_t)(kt & 3) * STAGEB;
        #pragma unroll
        for (int t = 0; t < 2; t++) {
            uint32_t af[4][4], bf[2][4];
            #pragma unroll
            for (int mt = 0; mt < 4; mt++) ldsm_x4(af[mt], as_ + offA[mt][t]);
            #pragma unroll
            for (int p = 0; p < 2; p++)    ldsm_x4(bf[p],  bs_ + offB[p][t]);
            #pragma unroll
            for (int mt = 0; mt < 4; mt++)
                #pragma unroll
                for (int nt = 0; nt < 4; nt++)
                    mma_f16(acc[mt][nt], af[mt],
                            bf[nt >> 1][(nt & 1) * 2], bf[nt >> 1][(nt & 1) * 2 + 1]);
        }
    }
#undef ISSUE_STAGE
}

// ---------------- GEMM1: fused qkv + lite projections, scatter epilogue ----------------
__global__ __launch_bounds__(256, 2)
void gemm1_kernel(const float* __restrict__ qkv_b) {
    __shared__ __align__(128) char smA[4 * STAGEB];
    __shared__ __align__(128) char smB[4 * STAGEB];
    const uint32_t aSm = (uint32_t)__cvta_generic_to_shared(smA);
    const uint32_t bSm = (uint32_t)__cvta_generic_to_shared(smB);
    const int m0 = blockIdx.y * 128;
    const int n0 = blockIdx.x * 128;

    float acc[4][4][4] = {};
    mma_tile_cp(g_x16 + (size_t)m0 * DIMC, DIMC,
                g_wB + (size_t)n0 * DIMC, DIMC, DIMC / 32, acc, aSm, bSm);

    const int lane = threadIdx.x & 31, warp = threadIdx.x >> 5;
    const int warpM = (warp >> 2) * 64, warpN = (warp & 3) * 32;
    const int row = lane >> 2, tg2 = (lane & 3) * 2;
    const bool is_qkv = (n0 < 1536);

    #pragma unroll
    for (int mt = 0; mt < 4; mt++) {
        #pragma unroll
        for (int half = 0; half < 2; half++) {
            int m = m0 + warpM + mt * 16 + row + half * 8;
            int b = m / NTOK, n = m - b * NTOK;
            #pragma unroll
            for (int nt = 0; nt < 4; nt++) {
                int c = n0 + warpN + nt * 8 + tg2;
                float v0 = acc[mt][nt][half * 2 + 0];
                float v1 = acc[mt][nt][half * 2 + 1];
                if (is_qkv) {
                    v0 += qkv_b[c];
                    v1 += qkv_b[c + 1];
                    int jj = c >> 9, hh = (c >> 5) & 15, d = c & 31;
                    float* dst = (jj == 0) ? g_q : ((jj == 1) ? g_k : g_v);
                    *(float2*)&dst[((size_t)(b * NHEADS + hh) * NTOK + n) * HD + d] =
                        make_float2(v0, v1);
                } else {
                    int cc = c - 1536;
                    int jj = cc >> 7, hh = (cc >> 3) & 15, d = cc & 7;
                    float* dst = (jj == 0) ? g_ql : ((jj == 1) ? g_kl : g_vl);
                    *(float2*)&dst[((size_t)(b * NHEADS + hh) * NTOK + n) * LHD + d] =
                        make_float2(v0, v1);
                }
            }
        }
    }
}

// ---------------- fused dual attention, one block per (b,h) ----------------
__global__ __launch_bounds__(256)
void attn_kernel(const float* __restrict__ mask,
                 const float* __restrict__ lam1p,
                 const float* __restrict__ lam2p) {
    __shared__ float sq[NTOK * HD];
    __shared__ float skT[HD * NTOK];
    __shared__ float sv[NTOK * HD];
    __shared__ float sql[NTOK * LHD];
    __shared__ float sklT[LHD * NTOK];
    __shared__ float svl[NTOK * LHD];
    __shared__ float sp[NNSQ];
    __shared__ float spl[NNSQ];
    __shared__ float sinv[2 * NTOK];

    const int bid = blockIdx.x;
    const int b = bid >> 4, h = bid & 15;
    const int win = b & (NWIN - 1);
    const int tid = threadIdx.x;
    const size_t base  = (size_t)bid * (NTOK * HD);
    const size_t basel = (size_t)bid * (NTOK * LHD);

    for (int idx = tid; idx < NTOK * HD; idx += 256) {
        sq[idx] = g_q[base + idx];
        int j = idx >> 5, d = idx & 31;
        skT[d * NTOK + j] = g_k[base + idx];
        sv[idx] = g_v[base + idx];
    }
    for (int idx = tid; idx < NTOK * LHD; idx += 256) {
        sql[idx] = g_ql[basel + idx];
        int j = idx >> 3, d = idx & 7;
        sklT[d * NTOK + j] = g_kl[basel + idx];
        svl[idx] = g_vl[basel + idx];
    }
    __syncthreads();

    const float scale   = 0.17677669529663687f;  // 32^-0.5
    const float scale_l = 0.35355339059327373f;  // 8^-0.5
    const float* bias_h = g_relbias + h * NNSQ;
    const float* mask_w = mask + win * NNSQ;

    for (int idx = tid; idx < NNSQ; idx += 256) {
        int i = idx / NTOK, j = idx - i * NTOK;
        float bm = bias_h[idx] + mask_w[idx];
        float dot = 0.f;
        #pragma unroll
        for (int d = 0; d < HD; d++) dot += sq[i * HD + d] * skT[d * NTOK + j];
        float dotl = 0.f;
        #pragma unroll
        for (int d = 0; d < LHD; d++) dotl += sql[i * LHD + d] * sklT[d * NTOK + j];
        sp[idx]  = dot  * scale   + bm;
        spl[idx] = dotl * scale_l + bm;
    }
    __syncthreads();

    // softmax: 2 lanes per row, exp stored unnormalized; 1/sum kept per row
    if (tid < 2 * NTOK * 2) {
        int g = tid >> 1, q = tid & 1;
        float* row = ((g < NTOK) ? sp + g * NTOK : spl + (g - NTOK) * NTOK);
        unsigned am = __activemask();
        float mx = -1e30f;
        for (int j = q; j < NTOK; j += 2) mx = fmaxf(mx, row[j]);
        mx = fmaxf(mx, __shfl_xor_sync(am, mx, 1));
        float s = 0.f;
        for (int j = q; j < NTOK; j += 2) {
            float e = __expf(row[j] - mx);
            row[j] = e;
            s += e;
        }
        s += __shfl_xor_sync(am, s, 1);
        if (q == 0) sinv[g] = 1.f / s;
    }
    __syncthreads();

    const float lam1 = 1.f / (1.f + __expf(-*lam1p));
    const float lam2 = 1.f / (1.f + __expf(-*lam2p));

    // PV (orig): 49x32 outputs, fp16 store (2 cols per thread-iter)
    for (int o = tid; o < NTOK * 16; o += 256) {
        int i = o >> 4, d2 = (o & 15) << 1;
        float s0 = 0.f, s1 = 0.f;
        #pragma unroll
        for (int j = 0; j < NTOK; j++) {
            float p = sp[i * NTOK + j];
            s0 += p * sv[j * HD + d2];
            s1 += p * sv[j * HD + d2 + 1];
        }
        float sc = sinv[i];
        __half2 hv = __floats2half2_rn(s0 * sc, s1 * sc);
        *(__half2*)&g_xo16[((size_t)(b * NTOK + i)) * DIMC + h * HD + d2] = hv;
    }
    // diff branch: 49x8 outputs
    for (int o = tid; o < NTOK * 4; o += 256) {
        int i = o >> 2, d2 = (o & 3) << 1;
        float c1 = lam1 * sinv[NTOK + i], c2 = lam2 * sinv[i];
        float s0 = 0.f, s1 = 0.f;
        #pragma unroll
        for (int j = 0; j < NTOK; j++) {
            float w = c1 * spl[i * NTOK + j] - c2 * sp[i * NTOK + j];
            s0 += w * svl[j * LHD + d2];
            s1 += w * svl[j * LHD + d2 + 1];
        }
        __half2 hv = __floats2half2_rn(s0, s1);
        *(__half2*)&g_dv16[((size_t)(b * NTOK + i)) * LDIM + h * LHD + d2] = hv;
    }
}

// ---------------- GEMM3: out = xo@Wp^T + dv@W2t^T + b2 ----------------
__global__ __launch_bounds__(256, 2)
void gemm3_kernel(float* __restrict__ out) {
    __shared__ __align__(128) char smA[4 * STAGEB];
    __shared__ __align__(128) char smB[4 * STAGEB];
    const uint32_t aSm = (uint32_t)__cvta_generic_to_shared(smA);
    const uint32_t bSm = (uint32_t)__cvta_generic_to_shared(smB);
    const int m0 = blockIdx.y * 128;
    const int n0 = blockIdx.x * 128;

    float acc[4][4][4] = {};
    mma_tile_cp(g_xo16 + (size_t)m0 * DIMC, DIMC,
                g_pw16 + (size_t)n0 * DIMC, DIMC, DIMC / 32, acc, aSm, bSm);
    mma_tile_cp(g_dv16 + (size_t)m0 * LDIM, LDIM,
                g_W2t16 + (size_t)n0 * LDIM, LDIM, LDIM / 32, acc, aSm, bSm);

    const int lane = threadIdx.x & 31, warp = threadIdx.x >> 5;
    const int warpM = (warp >> 2) * 64, warpN = (warp & 3) * 32;
    const int row = lane >> 2, tg2 = (lane & 3) * 2;

    #pragma unroll
    for (int nt = 0; nt < 4; nt++) {
        int c = n0 + warpN + nt * 8 + tg2;
        float b0 = g_b2[c], b1 = g_b2[c + 1];
        #pragma unroll
        for (int mt = 0; mt < 4; mt++) {
            #pragma unroll
            for (int half = 0; half < 2; half++) {
                int m = m0 + warpM + mt * 16 + row + half * 8;
                *(float2*)&out[(size_t)m * DIMC + c] =
                    make_float2(acc[mt][nt][half * 2 + 0] + b0,
                                acc[mt][nt][half * 2 + 1] + b1);
            }
        }
    }
}

// ---------------- launch ----------------
extern "C" void kernel_launch(void* const* d_in, const int* in_sizes, int n_in,
                              void* d_out, int out_size) {
    const float* x       = (const float*)d_in[0];
    const float* mask    = (const float*)d_in[1];
    const int*   rpi     = (const int*)  d_in[2];
    const float* table   = (const float*)d_in[3];
    const float* qkv_w   = (const float*)d_in[4];
    const float* qkv_b   = (const float*)d_in[5];
    const float* proj_w  = (const float*)d_in[6];
    const float* proj_b  = (const float*)d_in[7];
    const float* qlw     = (const float*)d_in[8];
    const float* klw     = (const float*)d_in[9];
    const float* vlw     = (const float*)d_in[10];
    const float* lam1p   = (const float*)d_in[11];
    const float* lam2p   = (const float*)d_in[12];
    const float* dpw     = (const float*)d_in[13];
    const float* dpb     = (const float*)d_in[14];
    const float* gamma_p = (const float*)d_in[15];
    float* out = (float*)d_out;

    conv_x_kernel<<<(int)((size_t)MROWS * DIMC / 4 / 256), 256>>>(x);
    conv_wB_kernel<<<NCOLS1 * DIMC / 4 / 256, 256>>>(qkv_w, qlw, klw, vlw);
    conv_pw_kernel<<<DIMC * DIMC / 4 / 256, 256>>>(proj_w);
    prep_bias_kernel<<<(NHEADS * NNSQ + 255) / 256, 256>>>(rpi, table);
    prep_w2_kernel<<<DIMC, LDIM>>>(dpw, proj_w, gamma_p);
    prep_b2_kernel<<<2, 256>>>(dpb, proj_w, proj_b, gamma_p);

    gemm1_kernel<<<dim3(NCOLS1 / 128, MROWS / 128), 256>>>(qkv_b);
    attn_kernel<<<NB * NHEADS, 256>>>(mask, lam1p, lam2p);
    gemm3_kernel<<<dim3(4, MROWS / 128), 256>>>(out);
}

// round 12
// speedup vs baseline: 3.9328x; 1.3930x over previous
#include <cuda_runtime.h>
#include <cuda_fp16.h>
#include <math.h>
#include <stdint.h>

// ---------------- problem constants ----------------
#define DIMC   512
#define NHEADS 16
#define HD     32
#define LHD    8
#define LDIM   128
#define NTOK   49
#define NB     2048
#define NWIN   64
#define MROWS  (NB*NTOK)        // 100352
#define NNSQ   (NTOK*NTOK)      // 2401
#define NCOLS1 1920             // 1536 qkv + 384 lite
#define STAGEB 8192             // bytes per stage per operand (128 rows x 64B)

// ---------------- device scratch (no allocations allowed) ----------------
__device__ __align__(256) __half g_q16 [(size_t)NB*NHEADS*NTOK*HD];
__device__ __align__(256) __half g_k16 [(size_t)NB*NHEADS*NTOK*HD];
__device__ __align__(256) __half g_v16 [(size_t)NB*NHEADS*NTOK*HD];
__device__ __align__(256) __half g_ql16[(size_t)NB*NHEADS*NTOK*LHD];
__device__ __align__(256) __half g_kl16[(size_t)NB*NHEADS*NTOK*LHD];
__device__ __align__(256) __half g_vl16[(size_t)NB*NHEADS*NTOK*LHD];
__device__ __align__(256) __half g_x16 [(size_t)MROWS*DIMC];
__device__ __align__(256) __half g_wB  [(size_t)NCOLS1*DIMC];   // packed qkv|ql|kl|vl
__device__ __align__(256) __half g_pw16[(size_t)DIMC*DIMC];
__device__ __align__(256) __half g_W2t16[DIMC*LDIM];
__device__ __align__(256) __half g_xo16[(size_t)MROWS*DIMC];
__device__ __align__(256) __half g_dv16[(size_t)MROWS*LDIM];
__device__ __align__(256) float  g_relbias[NHEADS*NNSQ];
__device__ __align__(256) float  g_b2 [DIMC];

// ---------------- conversion / prep kernels ----------------
__global__ void conv_x_kernel(const float* __restrict__ x) {
    size_t i4 = (size_t)blockIdx.x * 256 + threadIdx.x;     // float4 index
    float4 f = ((const float4*)x)[i4];
    __half2 h0 = __floats2half2_rn(f.x, f.y);
    __half2 h1 = __floats2half2_rn(f.z, f.w);
    ((uint2*)g_x16)[i4] = make_uint2(*(uint32_t*)&h0, *(uint32_t*)&h1);
}

__global__ void conv_wB_kernel(const float* __restrict__ qkv_w,
                               const float* __restrict__ qlw,
                               const float* __restrict__ klw,
                               const float* __restrict__ vlw) {
    int i4 = blockIdx.x * 256 + threadIdx.x;   // 0 .. 1920*512/4
    int row = i4 >> 7, col4 = i4 & 127;
    const float* src;
    if (row < 1536) src = qkv_w + (size_t)row * DIMC;
    else {
        int r2 = row - 1536, sel = r2 >> 7, lr = r2 & 127;
        src = ((sel == 0) ? qlw : (sel == 1) ? klw : vlw) + (size_t)lr * DIMC;
    }
    float4 f = ((const float4*)src)[col4];
    __half2 h0 = __floats2half2_rn(f.x, f.y);
    __half2 h1 = __floats2half2_rn(f.z, f.w);
    ((uint2*)g_wB)[i4] = make_uint2(*(uint32_t*)&h0, *(uint32_t*)&h1);
}

__global__ void conv_pw_kernel(const float* __restrict__ pw) {
    int i4 = blockIdx.x * 256 + threadIdx.x;
    float4 f = ((const float4*)pw)[i4];
    __half2 h0 = __floats2half2_rn(f.x, f.y);
    __half2 h1 = __floats2half2_rn(f.z, f.w);
    ((uint2*)g_pw16)[i4] = make_uint2(*(uint32_t*)&h0, *(uint32_t*)&h1);
}

__global__ void prep_bias_kernel(const int* __restrict__ rpi,
                                 const float* __restrict__ table) {
    int idx = blockIdx.x * 256 + threadIdx.x;
    if (idx < NHEADS * NNSQ) {
        int h = idx / NNSQ, ij = idx % NNSQ;
        g_relbias[idx] = table[rpi[ij] * NHEADS + h];
    }
}

__global__ void prep_w2_kernel(const float* __restrict__ dpw,
                               const float* __restrict__ pw,
                               const float* __restrict__ gamma_p) {
    int o = blockIdx.x, l = threadIdx.x;
    float s = 0.f;
    for (int c = 0; c < DIMC; c++)
        s += dpw[c * LDIM + l] * pw[o * DIMC + c];
    g_W2t16[o * LDIM + l] = __float2half_rn((*gamma_p) * s);
}

__global__ void prep_b2_kernel(const float* __restrict__ dpb,
                               const float* __restrict__ pw,
                               const float* __restrict__ pb,
                               const float* __restrict__ gamma_p) {
    int o = blockIdx.x * 256 + threadIdx.x;
    if (o < DIMC) {
        float s = 0.f;
        for (int c = 0; c < DIMC; c++) s += dpb[c] * pw[o * DIMC + c];
        g_b2[o] = pb[o] + (*gamma_p) * s;
    }
}

// ---------------- mma / cp.async helpers ----------------
__device__ __forceinline__ void mma_f16(float c[4], const uint32_t a[4],
                                        uint32_t b0, uint32_t b1) {
    asm volatile(
        "mma.sync.aligned.m16n8k16.row.col.f32.f16.f16.f32 "
        "{%0,%1,%2,%3}, {%4,%5,%6,%7}, {%8,%9}, {%0,%1,%2,%3};"
        : "+f"(c[0]), "+f"(c[1]), "+f"(c[2]), "+f"(c[3])
        : "r"(a[0]), "r"(a[1]), "r"(a[2]), "r"(a[3]), "r"(b0), "r"(b1));
}

__device__ __forceinline__ void ldsm_x4(uint32_t r[4], uint32_t saddr) {
    asm volatile("ldmatrix.sync.aligned.m8n8.x4.shared.b16 {%0,%1,%2,%3}, [%4];"
        : "=r"(r[0]), "=r"(r[1]), "=r"(r[2]), "=r"(r[3]) : "r"(saddr));
}

__device__ __forceinline__ void cpa16(uint32_t saddr, const void* g) {
    asm volatile("cp.async.cg.shared.global [%0], [%1], 16;" :: "r"(saddr), "l"(g));
}

// swizzled byte offset within an 8KB stage for (logical row r, k-octet kb)
__device__ __forceinline__ uint32_t swz(int r, int kb) {
    int s = r >> 1;
    int c = ((r & 1) << 2) | kb;
    return (uint32_t)((s << 7) + (((c ^ (s & 7)) << 4)));
}

// ---------------- cp.async fp16 mma GEMM tile core ----------------
__device__ __forceinline__ void mma_tile_cp(
        const __half* __restrict__ Ag, int lda,
        const __half* __restrict__ Bg, int ldb,
        int nk, float (&acc)[4][4][4],
        uint32_t aSm, uint32_t bSm) {
    const int tid = threadIdx.x;
    const int lane = tid & 31, warp = tid >> 5;
    const int warpM = (warp >> 2) * 64, warpN = (warp & 3) * 32;

    const int r0 = tid >> 2, kb0 = tid & 3;
    const __half* gA0 = Ag + (size_t)r0 * lda + kb0 * 8;
    const __half* gB0 = Bg + (size_t)r0 * ldb + kb0 * 8;
    const size_t a64 = (size_t)64 * lda, b64 = (size_t)64 * ldb;
    const uint32_t sA0 = aSm + swz(r0, kb0),      sA1 = aSm + swz(r0 + 64, kb0);
    const uint32_t sB0 = bSm + swz(r0, kb0),      sB1 = bSm + swz(r0 + 64, kb0);

    uint32_t offA[4][2], offB[2][2];
    {
        int rl = (lane & 7) + ((lane >> 3) & 1) * 8;
        int ka = lane >> 4;
        #pragma unroll
        for (int mt = 0; mt < 4; mt++)
            #pragma unroll
            for (int t = 0; t < 2; t++)
                offA[mt][t] = swz(warpM + mt * 16 + rl, 2 * t + ka);
        int rb = (lane & 7) + ((lane >> 4) & 1) * 8;
        int kbb = (lane >> 3) & 1;
        #pragma unroll
        for (int p = 0; p < 2; p++)
            #pragma unroll
            for (int t = 0; t < 2; t++)
                offB[p][t] = swz(warpN + p * 16 + rb, 2 * t + kbb);
    }

#define ISSUE_STAGE(S) do {                                           \
        int _s = (S);                                                 \
        if (_s < nk) {                                                \
            const __half* _ga = gA0 + _s * 32;                        \
            const __half* _gb = gB0 + _s * 32;                        \
            uint32_t _so = (uint32_t)(_s & 3) * STAGEB;               \
            cpa16(sA0 + _so, _ga); cpa16(sA1 + _so, _ga + a64);       \
            cpa16(sB0 + _so, _gb); cpa16(sB1 + _so, _gb + b64);       \
        }                                                             \
        asm volatile("cp.async.commit_group;");                       \
    } while (0)

    __syncthreads();   // smem may be in use by a previous call
    ISSUE_STAGE(0);
    ISSUE_STAGE(1);
    ISSUE_STAGE(2);

    for (int kt = 0; kt < nk; kt++) {
        asm volatile("cp.async.wait_group 2;");
        __syncthreads();
        ISSUE_STAGE(kt + 3);

        const uint32_t as_ = aSm + (uint32_t)(kt & 3) * STAGEB;
        const uint32_t bs_ = bSm + (uint32_t)(kt & 3) * STAGEB;
        #pragma unroll
        for (int t = 0; t < 2; t++) {
            uint32_t af[4][4], bf[2][4];
            #pragma unroll
            for (int mt = 0; mt < 4; mt++) ldsm_x4(af[mt], as_ + offA[mt][t]);
            #pragma unroll
            for (int p = 0; p < 2; p++)    ldsm_x4(bf[p],  bs_ + offB[p][t]);
            #pragma unroll
            for (int mt = 0; mt < 4; mt++)
                #pragma unroll
                for (int nt = 0; nt < 4; nt++)
                    mma_f16(acc[mt][nt], af[mt],
                            bf[nt >> 1][(nt & 1) * 2], bf[nt >> 1][(nt & 1) * 2 + 1]);
        }
    }
#undef ISSUE_STAGE
}

// ---------------- GEMM1: fused qkv + lite projections, fp16 scatter epilogue ----------------
__global__ __launch_bounds__(256, 2)
void gemm1_kernel(const float* __restrict__ qkv_b) {
    __shared__ __align__(128) char smA[4 * STAGEB];
    __shared__ __align__(128) char smB[4 * STAGEB];
    const uint32_t aSm = (uint32_t)__cvta_generic_to_shared(smA);
    const uint32_t bSm = (uint32_t)__cvta_generic_to_shared(smB);
    const int m0 = blockIdx.y * 128;
    const int n0 = blockIdx.x * 128;

    float acc[4][4][4] = {};
    mma_tile_cp(g_x16 + (size_t)m0 * DIMC, DIMC,
                g_wB + (size_t)n0 * DIMC, DIMC, DIMC / 32, acc, aSm, bSm);

    const int lane = threadIdx.x & 31, warp = threadIdx.x >> 5;
    const int warpM = (warp >> 2) * 64, warpN = (warp & 3) * 32;
    const int row = lane >> 2, tg2 = (lane & 3) * 2;
    const bool is_qkv = (n0 < 1536);

    #pragma unroll
    for (int mt = 0; mt < 4; mt++) {
        #pragma unroll
        for (int half = 0; half < 2; half++) {
            int m = m0 + warpM + mt * 16 + row + half * 8;
            int b = m / NTOK, n = m - b * NTOK;
            #pragma unroll
            for (int nt = 0; nt < 4; nt++) {
                int c = n0 + warpN + nt * 8 + tg2;
                float v0 = acc[mt][nt][half * 2 + 0];
                float v1 = acc[mt][nt][half * 2 + 1];
                if (is_qkv) {
                    v0 += qkv_b[c];
                    v1 += qkv_b[c + 1];
                    int jj = c >> 9, hh = (c >> 5) & 15, d = c & 31;
                    __half* dst = (jj == 0) ? g_q16 : ((jj == 1) ? g_k16 : g_v16);
                    __half2 hv = __floats2half2_rn(v0, v1);
                    *(__half2*)&dst[((size_t)(b * NHEADS + hh) * NTOK + n) * HD + d] = hv;
                } else {
                    int cc = c - 1536;
                    int jj = cc >> 7, hh = (cc >> 3) & 15, d = cc & 7;
                    __half* dst = (jj == 0) ? g_ql16 : ((jj == 1) ? g_kl16 : g_vl16);
                    __half2 hv = __floats2half2_rn(v0, v1);
                    *(__half2*)&dst[((size_t)(b * NHEADS + hh) * NTOK + n) * LHD + d] = hv;
                }
            }
        }
    }
}

// ---------------- fused dual attention, one block per (b,h) ----------------
// fp16 inputs, register-tiled QK (4x4 per thread), tiled PV, f32 accumulate.
#define QSTR 17   // half2 row stride for q/k (pad 16->17)
#define LSTR 5    // half2 row stride for ql/kl (pad 4->5)
#define PSTR 50   // float row stride for probability tiles

__global__ __launch_bounds__(256)
void attn_kernel(const float* __restrict__ mask,
                 const float* __restrict__ lam1p,
                 const float* __restrict__ lam2p) {
    __shared__ uint32_t sq2[NTOK * QSTR];
    __shared__ uint32_t sk2[NTOK * QSTR];
    __shared__ uint32_t sv2[NTOK * 16];
    __shared__ uint32_t sql2[NTOK * LSTR];
    __shared__ uint32_t skl2[NTOK * LSTR];
    __shared__ uint32_t svl2[NTOK * 4];
    __shared__ float sp[NTOK * PSTR];
    __shared__ float spl[NTOK * PSTR];
    __shared__ float sinv[2 * NTOK];

    const int bid = blockIdx.x;
    const int b = bid >> 4, h = bid & 15;
    const int win = b & (NWIN - 1);
    const int tid = threadIdx.x;
    const size_t base2  = (size_t)bid * (NTOK * 16);  // half2 units
    const size_t basel2 = (size_t)bid * (NTOK * 4);

    const uint32_t* gq = (const uint32_t*)g_q16 + base2;
    const uint32_t* gk = (const uint32_t*)g_k16 + base2;
    const uint32_t* gv = (const uint32_t*)g_v16 + base2;
    const uint32_t* gql = (const uint32_t*)g_ql16 + basel2;
    const uint32_t* gkl = (const uint32_t*)g_kl16 + basel2;
    const uint32_t* gvl = (const uint32_t*)g_vl16 + basel2;

    for (int idx = tid; idx < NTOK * 16; idx += 256) {
        int j = idx >> 4, dd = idx & 15;
        sq2[j * QSTR + dd] = gq[idx];
        sk2[j * QSTR + dd] = gk[idx];
        sv2[idx] = gv[idx];
    }
    for (int idx = tid; idx < NTOK * 4; idx += 256) {
        int j = idx >> 2, dd = idx & 3;
        sql2[j * LSTR + dd] = gql[idx];
        skl2[j * LSTR + dd] = gkl[idx];
        svl2[idx] = gvl[idx];
    }
    __syncthreads();

    const float scale   = 0.17677669529663687f;  // 32^-0.5
    const float scale_l = 0.35355339059327373f;  // 8^-0.5
    const float* bias_h = g_relbias + h * NNSQ;
    const float* mask_w = mask + win * NNSQ;

    // ---- QK: 13x13 grid of 4x4 tiles, one tile per thread ----
    if (tid < 169) {
        const int i0 = (tid / 13) * 4, j0 = (tid % 13) * 4;
        int ia[4], ja[4];
        #pragma unroll
        for (int a = 0; a < 4; a++) {
            ia[a] = (i0 + a < NTOK) ? (i0 + a) : (NTOK - 1);
            ja[a] = (j0 + a < NTOK) ? (j0 + a) : (NTOK - 1);
        }
        float acc[4][4] = {}, accl[4][4] = {};
        #pragma unroll
        for (int dd = 0; dd < 16; dd++) {
            float2 qa[4], kb[4];
            #pragma unroll
            for (int a = 0; a < 4; a++) {
                qa[a] = __half22float2(*(const __half2*)&sq2[ia[a] * QSTR + dd]);
                kb[a] = __half22float2(*(const __half2*)&sk2[ja[a] * QSTR + dd]);
            }
            #pragma unroll
            for (int a = 0; a < 4; a++)
                #pragma unroll
                for (int c = 0; c < 4; c++)
                    acc[a][c] += qa[a].x * kb[c].x + qa[a].y * kb[c].y;
        }
        #pragma unroll
        for (int dd = 0; dd < 4; dd++) {
            float2 qa[4], kb[4];
            #pragma unroll
            for (int a = 0; a < 4; a++) {
                qa[a] = __half22float2(*(const __half2*)&sql2[ia[a] * LSTR + dd]);
                kb[a] = __half22float2(*(const __half2*)&skl2[ja[a] * LSTR + dd]);
            }
            #pragma unroll
            for (int a = 0; a < 4; a++)
                #pragma unroll
                for (int c = 0; c < 4; c++)
                    accl[a][c] += qa[a].x * kb[c].x + qa[a].y * kb[c].y;
        }
        #pragma unroll
        for (int a = 0; a < 4; a++) {
            if (i0 + a >= NTOK) break;
            int i = i0 + a;
            #pragma unroll
            for (int c = 0; c < 4; c++) {
                if (j0 + c >= NTOK) break;
                int j = j0 + c;
                float bm = bias_h[i * NTOK + j] + mask_w[i * NTOK + j];
                sp [i * PSTR + j] = acc [a][c] * scale   + bm;
                spl[i * PSTR + j] = accl[a][c] * scale_l + bm;
            }
        }
    }
    __syncthreads();

    // ---- softmax: 2 lanes per row, store unnormalized exp + 1/sum ----
    if (tid < 2 * NTOK * 2) {
        int g = tid >> 1, q = tid & 1;
        float* row = ((g < NTOK) ? sp + g * PSTR : spl + (g - NTOK) * PSTR);
        unsigned am = __activemask();
        float mx = -1e30f;
        for (int j = q; j < NTOK; j += 2) mx = fmaxf(mx, row[j]);
        mx = fmaxf(mx, __shfl_xor_sync(am, mx, 1));
        float s = 0.f;
        for (int j = q; j < NTOK; j += 2) {
            float e = __expf(row[j] - mx);
            row[j] = e;
            s += e;
        }
        s += __shfl_xor_sync(am, s, 1);
        if (q == 0) sinv[g] = 1.f / s;
    }
    __syncthreads();

    const float lam1 = 1.f / (1.f + __expf(-*lam1p));
    const float lam2 = 1.f / (1.f + __expf(-*lam2p));

    // ---- PV (orig): thread = (i, quad of half2) -> 8 output cols, STG.128 ----
    if (tid < NTOK * 4) {
        int i = tid >> 2, q4 = tid & 3;          // q4: which 4-half2 group
        const float* prow = sp + i * PSTR;
        float a0 = 0.f, a1 = 0.f, a2 = 0.f, a3 = 0.f,
              a4 = 0.f, a5 = 0.f, a6 = 0.f, a7 = 0.f;
        const uint32_t* vcol = sv2 + q4 * 4;
        #pragma unroll 7
        for (int j = 0; j < NTOK; j++) {
            float p = prow[j];
            float2 v0 = __half22float2(*(const __half2*)&vcol[j * 16 + 0]);
            float2 v1 = __half22float2(*(const __half2*)&vcol[j * 16 + 1]);
            float2 v2 = __half22float2(*(const __half2*)&vcol[j * 16 + 2]);
            float2 v3 = __half22float2(*(const __half2*)&vcol[j * 16 + 3]);
            a0 += p * v0.x; a1 += p * v0.y; a2 += p * v1.x; a3 += p * v1.y;
            a4 += p * v2.x; a5 += p * v2.y; a6 += p * v3.x; a7 += p * v3.y;
        }
        float sc = sinv[i];
        __half2 h0 = __floats2half2_rn(a0 * sc, a1 * sc);
        __half2 h1 = __floats2half2_rn(a2 * sc, a3 * sc);
        __half2 h2 = __floats2half2_rn(a4 * sc, a5 * sc);
        __half2 h3 = __floats2half2_rn(a6 * sc, a7 * sc);
        uint4 pack = make_uint4(*(uint32_t*)&h0, *(uint32_t*)&h1,
                                *(uint32_t*)&h2, *(uint32_t*)&h3);
        *(uint4*)&g_xo16[((size_t)(b * NTOK + i)) * DIMC + h * HD + q4 * 8] = pack;
    }

    // ---- diff branch PV: thread = (i, half2 col) ----
    if (tid < NTOK * 4) {
        int i = tid >> 2, d2 = tid & 3;
        float c1 = lam1 * sinv[NTOK + i], c2 = lam2 * sinv[i];
        const float* prow  = sp  + i * PSTR;
        const float* plrow = spl + i * PSTR;
        float s0 = 0.f, s1 = 0.f;
        #pragma unroll 7
        for (int j = 0; j < NTOK; j++) {
            float w = c1 * plrow[j] - c2 * prow[j];
            float2 v = __half22float2(*(const __half2*)&svl2[j * 4 + d2]);
            s0 += w * v.x; s1 += w * v.y;
        }
        __half2 hv = __floats2half2_rn(s0, s1);
        *(__half2*)&g_dv16[((size_t)(b * NTOK + i)) * LDIM + h * LHD + d2 * 2] = hv;
    }
}

// ---------------- GEMM3: out = xo@Wp^T + dv@W2t^T + b2 ----------------
__global__ __launch_bounds__(256, 2)
void gemm3_kernel(float* __restrict__ out) {
    __shared__ __align__(128) char smA[4 * STAGEB];
    __shared__ __align__(128) char smB[4 * STAGEB];
    const uint32_t aSm = (uint32_t)__cvta_generic_to_shared(smA);
    const uint32_t bSm = (uint32_t)__cvta_generic_to_shared(smB);
    const int m0 = blockIdx.y * 128;
    const int n0 = blockIdx.x * 128;

    float acc[4][4][4] = {};
    mma_tile_cp(g_xo16 + (size_t)m0 * DIMC, DIMC,
                g_pw16 + (size_t)n0 * DIMC, DIMC, DIMC / 32, acc, aSm, bSm);
    mma_tile_cp(g_dv16 + (size_t)m0 * LDIM, LDIM,
                g_W2t16 + (size_t)n0 * LDIM, LDIM, LDIM / 32, acc, aSm, bSm);

    const int lane = threadIdx.x & 31, warp = threadIdx.x >> 5;
    const int warpM = (warp >> 2) * 64, warpN = (warp & 3) * 32;
    const int row = lane >> 2, tg2 = (lane & 3) * 2;

    #pragma unroll
    for (int nt = 0; nt < 4; nt++) {
        int c = n0 + warpN + nt * 8 + tg2;
        float b0 = g_b2[c], b1 = g_b2[c + 1];
        #pragma unroll
        for (int mt = 0; mt < 4; mt++) {
            #pragma unroll
            for (int half = 0; half < 2; half++) {
                int m = m0 + warpM + mt * 16 + row + half * 8;
                *(float2*)&out[(size_t)m * DIMC + c] =
                    make_float2(acc[mt][nt][half * 2 + 0] + b0,
                                acc[mt][nt][half * 2 + 1] + b1);
            }
        }
    }
}

// ---------------- launch ----------------
extern "C" void kernel_launch(void* const* d_in, const int* in_sizes, int n_in,
                              void* d_out, int out_size) {
    const float* x       = (const float*)d_in[0];
    const float* mask    = (const float*)d_in[1];
    const int*   rpi     = (const int*)  d_in[2];
    const float* table   = (const float*)d_in[3];
    const float* qkv_w   = (const float*)d_in[4];
    const float* qkv_b   = (const float*)d_in[5];
    const float* proj_w  = (const float*)d_in[6];
    const float* proj_b  = (const float*)d_in[7];
    const float* qlw     = (const float*)d_in[8];
    const float* klw     = (const float*)d_in[9];
    const float* vlw     = (const float*)d_in[10];
    const float* lam1p   = (const float*)d_in[11];
    const float* lam2p   = (const float*)d_in[12];
    const float* dpw     = (const float*)d_in[13];
    const float* dpb     = (const float*)d_in[14];
    const float* gamma_p = (const float*)d_in[15];
    float* out = (float*)d_out;

    conv_x_kernel<<<(int)((size_t)MROWS * DIMC / 4 / 256), 256>>>(x);
    conv_wB_kernel<<<NCOLS1 * DIMC / 4 / 256, 256>>>(qkv_w, qlw, klw, vlw);
    conv_pw_kernel<<<DIMC * DIMC / 4 / 256, 256>>>(proj_w);
    prep_bias_kernel<<<(NHEADS * NNSQ + 255) / 256, 256>>>(rpi, table);
    prep_w2_kernel<<<DIMC, LDIM>>>(dpw, proj_w, gamma_p);
    prep_b2_kernel<<<2, 256>>>(dpb, proj_w, proj_b, gamma_p);

    gemm1_kernel<<<dim3(NCOLS1 / 128, MROWS / 128), 256>>>(qkv_b);
    attn_kernel<<<NB * NHEADS, 256>>>(mask, lam1p, lam2p);
    gemm3_kernel<<<dim3(4, MROWS / 128), 256>>>(out);
}

// round 15
// speedup vs baseline: 4.2255x; 1.0744x over previous
#include <cuda_runtime.h>
#include <cuda_fp16.h>
#include <math.h>
#include <stdint.h>

// ---------------- problem constants ----------------
#define DIMC   512
#define NHEADS 16
#define HD     32
#define LHD    8
#define LDIM   128
#define NTOK   49
#define NB     2048
#define NWIN   64
#define MROWS  (NB*NTOK)        // 100352
#define NNSQ   (NTOK*NTOK)      // 2401
#define NCOLS1 1920             // 1536 qkv + 384 lite
#define STAGEB 8192             // bytes per stage per operand (128 rows x 64B)

// ---------------- device scratch (no allocations allowed) ----------------
__device__ __align__(256) __half g_q16 [(size_t)NB*NHEADS*NTOK*HD];
__device__ __align__(256) __half g_k16 [(size_t)NB*NHEADS*NTOK*HD];
__device__ __align__(256) __half g_v16 [(size_t)NB*NHEADS*NTOK*HD];
__device__ __align__(256) __half g_ql16[(size_t)NB*NHEADS*NTOK*LHD];
__device__ __align__(256) __half g_kl16[(size_t)NB*NHEADS*NTOK*LHD];
__device__ __align__(256) __half g_vl16[(size_t)NB*NHEADS*NTOK*LHD];
__device__ __align__(256) __half g_x16 [(size_t)MROWS*DIMC];
__device__ __align__(256) __half g_wB  [(size_t)NCOLS1*DIMC];   // packed qkv|ql|kl|vl
__device__ __align__(256) __half g_pw16[(size_t)DIMC*DIMC];
__device__ __align__(256) __half g_W2t16[DIMC*LDIM];
__device__ __align__(256) __half g_xo16[(size_t)MROWS*DIMC];
__device__ __align__(256) __half g_dv16[(size_t)MROWS*LDIM];
__device__ __align__(256) float  g_relbias[NHEADS*NNSQ];
__device__ __align__(256) float  g_b2 [DIMC];

// ---------------- conversion / prep kernels ----------------
__global__ void conv_x_kernel(const float* __restrict__ x) {
    size_t i4 = (size_t)blockIdx.x * 256 + threadIdx.x;     // float4 index
    float4 f = ((const float4*)x)[i4];
    __half2 h0 = __floats2half2_rn(f.x, f.y);
    __half2 h1 = __floats2half2_rn(f.z, f.w);
    ((uint2*)g_x16)[i4] = make_uint2(*(uint32_t*)&h0, *(uint32_t*)&h1);
}

__global__ void conv_wB_kernel(const float* __restrict__ qkv_w,
                               const float* __restrict__ qlw,
                               const float* __restrict__ klw,
                               const float* __restrict__ vlw) {
    int i4 = blockIdx.x * 256 + threadIdx.x;   // 0 .. 1920*512/4
    int row = i4 >> 7, col4 = i4 & 127;
    const float* src;
    if (row < 1536) src = qkv_w + (size_t)row * DIMC;
    else {
        int r2 = row - 1536, sel = r2 >> 7, lr = r2 & 127;
        src = ((sel == 0) ? qlw : (sel == 1) ? klw : vlw) + (size_t)lr * DIMC;
    }
    float4 f = ((const float4*)src)[col4];
    __half2 h0 = __floats2half2_rn(f.x, f.y);
    __half2 h1 = __floats2half2_rn(f.z, f.w);
    ((uint2*)g_wB)[i4] = make_uint2(*(uint32_t*)&h0, *(uint32_t*)&h1);
}

__global__ void conv_pw_kernel(const float* __restrict__ pw) {
    int i4 = blockIdx.x * 256 + threadIdx.x;
    float4 f = ((const float4*)pw)[i4];
    __half2 h0 = __floats2half2_rn(f.x, f.y);
    __half2 h1 = __floats2half2_rn(f.z, f.w);
    ((uint2*)g_pw16)[i4] = make_uint2(*(uint32_t*)&h0, *(uint32_t*)&h1);
}

__global__ void prep_bias_kernel(const int* __restrict__ rpi,
                                 const float* __restrict__ table) {
    int idx = blockIdx.x * 256 + threadIdx.x;
    if (idx < NHEADS * NNSQ) {
        int h = idx / NNSQ, ij = idx % NNSQ;
        g_relbias[idx] = table[rpi[ij] * NHEADS + h];
    }
}

__global__ void prep_w2_kernel(const float* __restrict__ dpw,
                               const float* __restrict__ pw,
                               const float* __restrict__ gamma_p) {
    int o = blockIdx.x, l = threadIdx.x;
    float s = 0.f;
    for (int c = 0; c < DIMC; c++)
        s += dpw[c * LDIM + l] * pw[o * DIMC + c];
    g_W2t16[o * LDIM + l] = __float2half_rn((*gamma_p) * s);
}

__global__ void prep_b2_kernel(const float* __restrict__ dpb,
                               const float* __restrict__ pw,
                               const float* __restrict__ pb,
                               const float* __restrict__ gamma_p) {
    int o = blockIdx.x * 256 + threadIdx.x;
    if (o < DIMC) {
        float s = 0.f;
        for (int c = 0; c < DIMC; c++) s += dpb[c] * pw[o * DIMC + c];
        g_b2[o] = pb[o] + (*gamma_p) * s;
    }
}

// ---------------- mma / cp.async helpers ----------------
__device__ __forceinline__ void mma_f16(float c[4], const uint32_t a[4],
                                        uint32_t b0, uint32_t b1) {
    asm volatile(
        "mma.sync.aligned.m16n8k16.row.col.f32.f16.f16.f32 "
        "{%0,%1,%2,%3}, {%4,%5,%6,%7}, {%8,%9}, {%0,%1,%2,%3};"
        : "+f"(c[0]), "+f"(c[1]), "+f"(c[2]), "+f"(c[3])
        : "r"(a[0]), "r"(a[1]), "r"(a[2]), "r"(a[3]), "r"(b0), "r"(b1));
}

__device__ __forceinline__ void ldsm_x4(uint32_t r[4], uint32_t saddr) {
    asm volatile("ldmatrix.sync.aligned.m8n8.x4.shared.b16 {%0,%1,%2,%3}, [%4];"
        : "=r"(r[0]), "=r"(r[1]), "=r"(r[2]), "=r"(r[3]) : "r"(saddr));
}

__device__ __forceinline__ void cpa16(uint32_t saddr, const void* g) {
    asm volatile("cp.async.cg.shared.global [%0], [%1], 16;" :: "r"(saddr), "l"(g));
}

// swizzled byte offset within an 8KB stage for (logical row r, k-octet kb)
__device__ __forceinline__ uint32_t swz(int r, int kb) {
    int s = r >> 1;
    int c = ((r & 1) << 2) | kb;
    return (uint32_t)((s << 7) + (((c ^ (s & 7)) << 4)));
}

// ---------------- cp.async fp16 mma GEMM tile core (NK compile-time) ----------------
template <int NK>
__device__ __forceinline__ void mma_tile_cp(
        const __half* __restrict__ Ag, int lda,
        const __half* __restrict__ Bg, int ldb,
        float (&acc)[4][4][4],
        uint32_t aSm, uint32_t bSm) {
    const int tid = threadIdx.x;
    const int lane = tid & 31, warp = tid >> 5;
    const int warpM = (warp >> 2) * 64, warpN = (warp & 3) * 32;

    const int r0 = tid >> 2, kb0 = tid & 3;
    const __half* gA0 = Ag + (size_t)r0 * lda + kb0 * 8;
    const __half* gB0 = Bg + (size_t)r0 * ldb + kb0 * 8;
    const size_t a64 = (size_t)64 * lda, b64 = (size_t)64 * ldb;
    const uint32_t sA0 = aSm + swz(r0, kb0),      sA1 = aSm + swz(r0 + 64, kb0);
    const uint32_t sB0 = bSm + swz(r0, kb0),      sB1 = bSm + swz(r0 + 64, kb0);

    uint32_t offA[4][2], offB[2][2];
    {
        int rl = (lane & 7) + ((lane >> 3) & 1) * 8;
        int ka = lane >> 4;
        #pragma unroll
        for (int mt = 0; mt < 4; mt++)
            #pragma unroll
            for (int t = 0; t < 2; t++)
                offA[mt][t] = swz(warpM + mt * 16 + rl, 2 * t + ka);
        int rb = (lane & 7) + ((lane >> 4) & 1) * 8;
        int kbb = (lane >> 3) & 1;
        #pragma unroll
        for (int p = 0; p < 2; p++)
            #pragma unroll
            for (int t = 0; t < 2; t++)
                offB[p][t] = swz(warpN + p * 16 + rb, 2 * t + kbb);
    }

#define ISSUE_STAGE(S) do {                                           \
        int _s = (S);                                                 \
        if (_s < NK) {                                                \
            const __half* _ga = gA0 + _s * 32;                        \
            const __half* _gb = gB0 + _s * 32;                        \
            uint32_t _so = (uint32_t)(_s & 3) * STAGEB;               \
            cpa16(sA0 + _so, _ga); cpa16(sA1 + _so, _ga + a64);       \
            cpa16(sB0 + _so, _gb); cpa16(sB1 + _so, _gb + b64);       \
        }                                                             \
        asm volatile("cp.async.commit_group;");                       \
    } while (0)

    __syncthreads();   // smem may be in use by a previous call
    ISSUE_STAGE(0);
    ISSUE_STAGE(1);
    ISSUE_STAGE(2);

    #pragma unroll
    for (int kt = 0; kt < NK; kt++) {
        asm volatile("cp.async.wait_group 2;");
        __syncthreads();
        ISSUE_STAGE(kt + 3);

        const uint32_t as_ = aSm + (uint32_t)(kt & 3) * STAGEB;
        const uint32_t bs_ = bSm + (uint32_t)(kt & 3) * STAGEB;
        #pragma unroll
        for (int t = 0; t < 2; t++) {
            uint32_t af[4][4], bf[2][4];
            #pragma unroll
            for (int mt = 0; mt < 4; mt++) ldsm_x4(af[mt], as_ + offA[mt][t]);
            #pragma unroll
            for (int p = 0; p < 2; p++)    ldsm_x4(bf[p],  bs_ + offB[p][t]);
            #pragma unroll
            for (int mt = 0; mt < 4; mt++)
                #pragma unroll
                for (int nt = 0; nt < 4; nt++)
                    mma_f16(acc[mt][nt], af[mt],
                            bf[nt >> 1][(nt & 1) * 2], bf[nt >> 1][(nt & 1) * 2 + 1]);
        }
    }
#undef ISSUE_STAGE
}

// ---------------- GEMM1: fused qkv + lite projections, fp16 scatter epilogue ----------------
__global__ __launch_bounds__(256, 2)
void gemm1_kernel(const float* __restrict__ qkv_b) {
    __shared__ __align__(128) char smA[4 * STAGEB];
    __shared__ __align__(128) char smB[4 * STAGEB];
    const uint32_t aSm = (uint32_t)__cvta_generic_to_shared(smA);
    const uint32_t bSm = (uint32_t)__cvta_generic_to_shared(smB);
    const int m0 = blockIdx.y * 128;
    const int n0 = blockIdx.x * 128;

    float acc[4][4][4] = {};
    mma_tile_cp<DIMC / 32>(g_x16 + (size_t)m0 * DIMC, DIMC,
                           g_wB + (size_t)n0 * DIMC, DIMC, acc, aSm, bSm);

    const int lane = threadIdx.x & 31, warp = threadIdx.x >> 5;
    const int warpM = (warp >> 2) * 64, warpN = (warp & 3) * 32;
    const int row = lane >> 2, tg2 = (lane & 3) * 2;
    const bool is_qkv = (n0 < 1536);

    #pragma unroll
    for (int mt = 0; mt < 4; mt++) {
        #pragma unroll
        for (int half = 0; half < 2; half++) {
            int m = m0 + warpM + mt * 16 + row + half * 8;
            int b = m / NTOK, n = m - b * NTOK;
            #pragma unroll
            for (int nt = 0; nt < 4; nt++) {
                int c = n0 + warpN + nt * 8 + tg2;
                float v0 = acc[mt][nt][half * 2 + 0];
                float v1 = acc[mt][nt][half * 2 + 1];
                if (is_qkv) {
                    v0 += qkv_b[c];
                    v1 += qkv_b[c + 1];
                    int jj = c >> 9, hh = (c >> 5) & 15, d = c & 31;
                    __half* dst = (jj == 0) ? g_q16 : ((jj == 1) ? g_k16 : g_v16);
                    __half2 hv = __floats2half2_rn(v0, v1);
                    *(__half2*)&dst[((size_t)(b * NHEADS + hh) * NTOK + n) * HD + d] = hv;
                } else {
                    int cc = c - 1536;
                    int jj = cc >> 7, hh = (cc >> 3) & 15, d = cc & 7;
                    __half* dst = (jj == 0) ? g_ql16 : ((jj == 1) ? g_kl16 : g_vl16);
                    __half2 hv = __floats2half2_rn(v0, v1);
                    *(__half2*)&dst[((size_t)(b * NHEADS + hh) * NTOK + n) * LHD + d] = hv;
                }
            }
        }
    }
}

// ---------------- fused dual attention, one block per (b,h) ----------------
#define QSTR 17   // half2 row stride for q/k (pad 16->17)
#define LSTR 5    // half2 row stride for ql/kl (pad 4->5)
#define PSTR 50   // float row stride for probability tiles

__global__ __launch_bounds__(256)
void attn_kernel(const float* __restrict__ mask,
                 const float* __restrict__ lam1p,
                 const float* __restrict__ lam2p) {
    __shared__ uint32_t sq2[NTOK * QSTR];
    __shared__ uint32_t sk2[NTOK * QSTR];
    __shared__ uint32_t sv2[NTOK * 16];
    __shared__ uint32_t sql2[NTOK * LSTR];
    __shared__ uint32_t skl2[NTOK * LSTR];
    __shared__ uint32_t svl2[NTOK * 4];
    __shared__ float sp[NTOK * PSTR];
    __shared__ float spl[NTOK * PSTR];
    __shared__ float sinv[2 * NTOK];

    const int bid = blockIdx.x;
    const int b = bid >> 4, h = bid & 15;
    const int win = b & (NWIN - 1);
    const int tid = threadIdx.x;
    const size_t base2  = (size_t)bid * (NTOK * 16);  // half2 units
    const size_t basel2 = (size_t)bid * (NTOK * 4);

    const uint32_t* gq = (const uint32_t*)g_q16 + base2;
    const uint32_t* gk = (const uint32_t*)g_k16 + base2;
    const uint32_t* gv = (const uint32_t*)g_v16 + base2;
    const uint32_t* gql = (const uint32_t*)g_ql16 + basel2;
    const uint32_t* gkl = (const uint32_t*)g_kl16 + basel2;
    const uint32_t* gvl = (const uint32_t*)g_vl16 + basel2;

    for (int idx = tid; idx < NTOK * 16; idx += 256) {
        int j = idx >> 4, dd = idx & 15;
        sq2[j * QSTR + dd] = gq[idx];
        sk2[j * QSTR + dd] = gk[idx];
        sv2[idx] = gv[idx];
    }
    for (int idx = tid; idx < NTOK * 4; idx += 256) {
        int j = idx >> 2, dd = idx & 3;
        sql2[j * LSTR + dd] = gql[idx];
        skl2[j * LSTR + dd] = gkl[idx];
        svl2[idx] = gvl[idx];
    }
    __syncthreads();

    const float scale   = 0.17677669529663687f;  // 32^-0.5
    const float scale_l = 0.35355339059327373f;  // 8^-0.5
    const float* bias_h = g_relbias + h * NNSQ;
    const float* mask_w = mask + win * NNSQ;

    // ---- QK: 13x13 grid of 4x4 tiles, one tile per thread ----
    if (tid < 169) {
        const int i0 = (tid / 13) * 4, j0 = (tid % 13) * 4;
        int ia[4], ja[4];
        #pragma unroll
        for (int a = 0; a < 4; a++) {
            ia[a] = (i0 + a < NTOK) ? (i0 + a) : (NTOK - 1);
            ja[a] = (j0 + a < NTOK) ? (j0 + a) : (NTOK - 1);
        }
        float acc[4][4] = {}, accl[4][4] = {};
        #pragma unroll
        for (int dd = 0; dd < 16; dd++) {
            float2 qa[4], kb[4];
            #pragma unroll
            for (int a = 0; a < 4; a++) {
                qa[a] = __half22float2(*(const __half2*)&sq2[ia[a] * QSTR + dd]);
                kb[a] = __half22float2(*(const __half2*)&sk2[ja[a] * QSTR + dd]);
            }
            #pragma unroll
            for (int a = 0; a < 4; a++)
                #pragma unroll
                for (int c = 0; c < 4; c++)
                    acc[a][c] += qa[a].x * kb[c].x + qa[a].y * kb[c].y;
        }
        #pragma unroll
        for (int dd = 0; dd < 4; dd++) {
            float2 qa[4], kb[4];
            #pragma unroll
            for (int a = 0; a < 4; a++) {
                qa[a] = __half22float2(*(const __half2*)&sql2[ia[a] * LSTR + dd]);
                kb[a] = __half22float2(*(const __half2*)&skl2[ja[a] * LSTR + dd]);
            }
            #pragma unroll
            for (int a = 0; a < 4; a++)
                #pragma unroll
                for (int c = 0; c < 4; c++)
                    accl[a][c] += qa[a].x * kb[c].x + qa[a].y * kb[c].y;
        }
        #pragma unroll
        for (int a = 0; a < 4; a++) {
            if (i0 + a >= NTOK) break;
            int i = i0 + a;
            #pragma unroll
            for (int c = 0; c < 4; c++) {
                if (j0 + c >= NTOK) break;
                int j = j0 + c;
                float bm = bias_h[i * NTOK + j] + mask_w[i * NTOK + j];
                sp [i * PSTR + j] = acc [a][c] * scale   + bm;
                spl[i * PSTR + j] = accl[a][c] * scale_l + bm;
            }
        }
    }
    __syncthreads();

    // ---- softmax: 2 lanes per row, store unnormalized exp + 1/sum ----
    if (tid < 2 * NTOK * 2) {
        int g = tid >> 1, q = tid & 1;
        float* row = ((g < NTOK) ? sp + g * PSTR : spl + (g - NTOK) * PSTR);
        unsigned am = __activemask();
        float mx = -1e30f;
        for (int j = q; j < NTOK; j += 2) mx = fmaxf(mx, row[j]);
        mx = fmaxf(mx, __shfl_xor_sync(am, mx, 1));
        float s = 0.f;
        for (int j = q; j < NTOK; j += 2) {
            float e = __expf(row[j] - mx);
            row[j] = e;
            s += e;
        }
        s += __shfl_xor_sync(am, s, 1);
        if (q == 0) sinv[g] = 1.f / s;
    }
    __syncthreads();

    const float lam1 = 1.f / (1.f + __expf(-*lam1p));
    const float lam2 = 1.f / (1.f + __expf(-*lam2p));

    // ---- PV (orig): thread = (i, quad of half2) -> 8 output cols, STG.128 ----
    if (tid < NTOK * 4) {
        int i = tid >> 2, q4 = tid & 3;
        const float* prow = sp + i * PSTR;
        float a0 = 0.f, a1 = 0.f, a2 = 0.f, a3 = 0.f,
              a4 = 0.f, a5 = 0.f, a6 = 0.f, a7 = 0.f;
        const uint32_t* vcol = sv2 + q4 * 4;
        #pragma unroll 7
        for (int j = 0; j < NTOK; j++) {
            float p = prow[j];
            float2 v0 = __half22float2(*(const __half2*)&vcol[j * 16 + 0]);
            float2 v1 = __half22float2(*(const __half2*)&vcol[j * 16 + 1]);
            float2 v2 = __half22float2(*(const __half2*)&vcol[j * 16 + 2]);
            float2 v3 = __half22float2(*(const __half2*)&vcol[j * 16 + 3]);
            a0 += p * v0.x; a1 += p * v0.y; a2 += p * v1.x; a3 += p * v1.y;
            a4 += p * v2.x; a5 += p * v2.y; a6 += p * v3.x; a7 += p * v3.y;
        }
        float sc = sinv[i];
        __half2 h0 = __floats2half2_rn(a0 * sc, a1 * sc);
        __half2 h1 = __floats2half2_rn(a2 * sc, a3 * sc);
        __half2 h2 = __floats2half2_rn(a4 * sc, a5 * sc);
        __half2 h3 = __floats2half2_rn(a6 * sc, a7 * sc);
        uint4 pack = make_uint4(*(uint32_t*)&h0, *(uint32_t*)&h1,
                                *(uint32_t*)&h2, *(uint32_t*)&h3);
        *(uint4*)&g_xo16[((size_t)(b * NTOK + i)) * DIMC + h * HD + q4 * 8] = pack;
    }

    // ---- diff branch PV: thread = (i, half2 col) ----
    if (tid < NTOK * 4) {
        int i = tid >> 2, d2 = tid & 3;
        float c1 = lam1 * sinv[NTOK + i], c2 = lam2 * sinv[i];
        const float* prow  = sp  + i * PSTR;
        const float* plrow = spl + i * PSTR;
        float s0 = 0.f, s1 = 0.f;
        #pragma unroll 7
        for (int j = 0; j < NTOK; j++) {
            float w = c1 * plrow[j] - c2 * prow[j];
            float2 v = __half22float2(*(const __half2*)&svl2[j * 4 + d2]);
            s0 += w * v.x; s1 += w * v.y;
        }
        __half2 hv = __floats2half2_rn(s0, s1);
        *(__half2*)&g_dv16[((size_t)(b * NTOK + i)) * LDIM + h * LHD + d2 * 2] = hv;
    }
}

// ---------------- GEMM3: out = xo@Wp^T + dv@W2t^T + b2 ----------------
__global__ __launch_bounds__(256, 2)
void gemm3_kernel(float* __restrict__ out) {
    __shared__ __align__(128) char smA[4 * STAGEB];
    __shared__ __align__(128) char smB[4 * STAGEB];
    const uint32_t aSm = (uint32_t)__cvta_generic_to_shared(smA);
    const uint32_t bSm = (uint32_t)__cvta_generic_to_shared(smB);
    const int m0 = blockIdx.y * 128;
    const int n0 = blockIdx.x * 128;

    float acc[4][4][4] = {};
    mma_tile_cp<DIMC / 32>(g_xo16 + (size_t)m0 * DIMC, DIMC,
                           g_pw16 + (size_t)n0 * DIMC, DIMC, acc, aSm, bSm);
    mma_tile_cp<LDIM / 32>(g_dv16 + (size_t)m0 * LDIM, LDIM,
                           g_W2t16 + (size_t)n0 * LDIM, LDIM, acc, aSm, bSm);

    const int lane = threadIdx.x & 31, warp = threadIdx.x >> 5;
    const int warpM = (warp >> 2) * 64, warpN = (warp & 3) * 32;
    const int row = lane >> 2, tg2 = (lane & 3) * 2;

    #pragma unroll
    for (int nt = 0; nt < 4; nt++) {
        int c = n0 + warpN + nt * 8 + tg2;
        float b0 = g_b2[c], b1 = g_b2[c + 1];
        #pragma unroll
        for (int mt = 0; mt < 4; mt++) {
            #pragma unroll
            for (int half = 0; half < 2; half++) {
                int m = m0 + warpM + mt * 16 + row + half * 8;
                *(float2*)&out[(size_t)m * DIMC + c] =
                    make_float2(acc[mt][nt][half * 2 + 0] + b0,
                                acc[mt][nt][half * 2 + 1] + b1);
            }
        }
    }
}

// ---------------- launch ----------------
// Launch order puts gemm1 6th so ncu (-s 5 -c 1) profiles it.
extern "C" void kernel_launch(void* const* d_in, const int* in_sizes, int n_in,
                              void* d_out, int out_size) {
    const float* x       = (const float*)d_in[0];
    const float* mask    = (const float*)d_in[1];
    const int*   rpi     = (const int*)  d_in[2];
    const float* table   = (const float*)d_in[3];
    const float* qkv_w   = (const float*)d_in[4];
    const float* qkv_b   = (const float*)d_in[5];
    const float* proj_w  = (const float*)d_in[6];
    const float* proj_b  = (const float*)d_in[7];
    const float* qlw     = (const float*)d_in[8];
    const float* klw     = (const float*)d_in[9];
    const float* vlw     = (const float*)d_in[10];
    const float* lam1p   = (const float*)d_in[11];
    const float* lam2p   = (const float*)d_in[12];
    const float* dpw     = (const float*)d_in[13];
    const float* dpb     = (const float*)d_in[14];
    const float* gamma_p = (const float*)d_in[15];
    float* out = (float*)d_out;

    conv_x_kernel<<<(int)((size_t)MROWS * DIMC / 4 / 256), 256>>>(x);
    conv_wB_kernel<<<NCOLS1 * DIMC / 4 / 256, 256>>>(qkv_w, qlw, klw, vlw);
    conv_pw_kernel<<<DIMC * DIMC / 4 / 256, 256>>>(proj_w);
    prep_bias_kernel<<<(NHEADS * NNSQ + 255) / 256, 256>>>(rpi, table);
    prep_w2_kernel<<<DIMC, LDIM>>>(dpw, proj_w, gamma_p);

    gemm1_kernel<<<dim3(NCOLS1 / 128, MROWS / 128), 256>>>(qkv_b);   // 6th launch -> ncu target

    prep_b2_kernel<<<2, 256>>>(dpb, proj_w, proj_b, gamma_p);        // only needed by gemm3
    attn_kernel<<<NB * NHEADS, 256>>>(mask, lam1p, lam2p);
    gemm3_kernel<<<dim3(4, MROWS / 128), 256>>>(out);
}

// round 17
// speedup vs baseline: 4.4122x; 1.0442x over previous
#include <cuda_runtime.h>
#include <cuda_fp16.h>
#include <math.h>
#include <stdint.h>

// ---------------- problem constants ----------------
#define DIMC   512
#define NHEADS 16
#define HD     32
#define LHD    8
#define LDIM   128
#define NTOK   49
#define NB     2048
#define NWIN   64
#define MROWS  (NB*NTOK)        // 100352
#define NNSQ   (NTOK*NTOK)      // 2401
#define NCOLS1 1920             // 1536 qkv + 384 lite
#define STAGEB 8192             // bytes per stage per operand (128 rows x 64B)

// ---------------- device scratch (no allocations allowed) ----------------
__device__ __align__(256) __half g_q16 [(size_t)NB*NHEADS*NTOK*HD];
__device__ __align__(256) __half g_k16 [(size_t)NB*NHEADS*NTOK*HD];
__device__ __align__(256) __half g_v16 [(size_t)NB*NHEADS*NTOK*HD];
__device__ __align__(256) __half g_ql16[(size_t)NB*NHEADS*NTOK*LHD];
__device__ __align__(256) __half g_kl16[(size_t)NB*NHEADS*NTOK*LHD];
__device__ __align__(256) __half g_vl16[(size_t)NB*NHEADS*NTOK*LHD];
__device__ __align__(256) __half g_x16 [(size_t)MROWS*DIMC];
__device__ __align__(256) __half g_wB  [(size_t)NCOLS1*DIMC];   // packed qkv|ql|kl|vl
__device__ __align__(256) __half g_pw16[(size_t)DIMC*DIMC];
__device__ __align__(256) __half g_W2t16[DIMC*LDIM];
__device__ __align__(256) __half g_xo16[(size_t)MROWS*DIMC];
__device__ __align__(256) __half g_dv16[(size_t)MROWS*LDIM];
__device__ __align__(256) float  g_relbias[NHEADS*NNSQ];
__device__ __align__(256) float  g_b2 [DIMC];

// ---------------- conversion / prep kernels ----------------
__global__ void conv_x_kernel(const float* __restrict__ x) {
    size_t i4 = (size_t)blockIdx.x * 256 + threadIdx.x;     // float4 index
    float4 f = ((const float4*)x)[i4];
    __half2 h0 = __floats2half2_rn(f.x, f.y);
    __half2 h1 = __floats2half2_rn(f.z, f.w);
    ((uint2*)g_x16)[i4] = make_uint2(*(uint32_t*)&h0, *(uint32_t*)&h1);
}

__global__ void conv_wB_kernel(const float* __restrict__ qkv_w,
                               const float* __restrict__ qlw,
                               const float* __restrict__ klw,
                               const float* __restrict__ vlw) {
    int i4 = blockIdx.x * 256 + threadIdx.x;   // 0 .. 1920*512/4
    int row = i4 >> 7, col4 = i4 & 127;
    const float* src;
    if (row < 1536) src = qkv_w + (size_t)row * DIMC;
    else {
        int r2 = row - 1536, sel = r2 >> 7, lr = r2 & 127;
        src = ((sel == 0) ? qlw : (sel == 1) ? klw : vlw) + (size_t)lr * DIMC;
    }
    float4 f = ((const float4*)src)[col4];
    __half2 h0 = __floats2half2_rn(f.x, f.y);
    __half2 h1 = __floats2half2_rn(f.z, f.w);
    ((uint2*)g_wB)[i4] = make_uint2(*(uint32_t*)&h0, *(uint32_t*)&h1);
}

__global__ void conv_pw_kernel(const float* __restrict__ pw) {
    int i4 = blockIdx.x * 256 + threadIdx.x;
    float4 f = ((const float4*)pw)[i4];
    __half2 h0 = __floats2half2_rn(f.x, f.y);
    __half2 h1 = __floats2half2_rn(f.z, f.w);
    ((uint2*)g_pw16)[i4] = make_uint2(*(uint32_t*)&h0, *(uint32_t*)&h1);
}

__global__ void prep_bias_kernel(const int* __restrict__ rpi,
                                 const float* __restrict__ table) {
    int idx = blockIdx.x * 256 + threadIdx.x;
    if (idx < NHEADS * NNSQ) {
        int h = idx / NNSQ, ij = idx % NNSQ;
        g_relbias[idx] = table[rpi[ij] * NHEADS + h];
    }
}

__global__ void prep_w2_kernel(const float* __restrict__ dpw,
                               const float* __restrict__ pw,
                               const float* __restrict__ gamma_p) {
    int o = blockIdx.x, l = threadIdx.x;
    float s = 0.f;
    for (int c = 0; c < DIMC; c++)
        s += dpw[c * LDIM + l] * pw[o * DIMC + c];
    g_W2t16[o * LDIM + l] = __float2half_rn((*gamma_p) * s);
}

__global__ void prep_b2_kernel(const float* __restrict__ dpb,
                               const float* __restrict__ pw,
                               const float* __restrict__ pb,
                               const float* __restrict__ gamma_p) {
    int o = blockIdx.x * 256 + threadIdx.x;
    if (o < DIMC) {
        float s = 0.f;
        for (int c = 0; c < DIMC; c++) s += dpb[c] * pw[o * DIMC + c];
        g_b2[o] = pb[o] + (*gamma_p) * s;
    }
}

// ---------------- mma / cp.async helpers ----------------
__device__ __forceinline__ void mma_f16(float c[4], const uint32_t a[4],
                                        uint32_t b0, uint32_t b1) {
    asm volatile(
        "mma.sync.aligned.m16n8k16.row.col.f32.f16.f16.f32 "
        "{%0,%1,%2,%3}, {%4,%5,%6,%7}, {%8,%9}, {%0,%1,%2,%3};"
        : "+f"(c[0]), "+f"(c[1]), "+f"(c[2]), "+f"(c[3])
        : "r"(a[0]), "r"(a[1]), "r"(a[2]), "r"(a[3]), "r"(b0), "r"(b1));
}

__device__ __forceinline__ void ldsm_x4(uint32_t r[4], uint32_t saddr) {
    asm volatile("ldmatrix.sync.aligned.m8n8.x4.shared.b16 {%0,%1,%2,%3}, [%4];"
        : "=r"(r[0]), "=r"(r[1]), "=r"(r[2]), "=r"(r[3]) : "r"(saddr));
}

__device__ __forceinline__ void cpa16(uint32_t saddr, const void* g) {
    asm volatile("cp.async.cg.shared.global [%0], [%1], 16;" :: "r"(saddr), "l"(g));
}

// swizzled byte offset for 64B-row tiles (2 logical rows per 128B smem line)
__device__ __forceinline__ uint32_t swz(int r, int kb) {
    int s = r >> 1;
    int c = ((r & 1) << 2) | kb;
    return (uint32_t)((s << 7) + (((c ^ (s & 7)) << 4)));
}

// swizzled byte offset for 128B-row tiles
__device__ __forceinline__ uint32_t sw128(int r, int oct) {
    return (uint32_t)((r << 7) + (((oct ^ (r & 7)) << 4)));
}
// scalar half address in a 128B-row swizzled tile (row r, col j)
__device__ __forceinline__ uint32_t sw128h(int r, int j) {
    return sw128(r, j >> 3) + (uint32_t)((j & 7) * 2);
}

// ---------------- cp.async fp16 mma GEMM tile core (NK compile-time) ----------------
template <int NK>
__device__ __forceinline__ void mma_tile_cp(
        const __half* __restrict__ Ag, int lda,
        const __half* __restrict__ Bg, int ldb,
        float (&acc)[4][4][4],
        uint32_t aSm, uint32_t bSm) {
    const int tid = threadIdx.x;
    const int lane = tid & 31, warp = tid >> 5;
    const int warpM = (warp >> 2) * 64, warpN = (warp & 3) * 32;

    const int r0 = tid >> 2, kb0 = tid & 3;
    const __half* gA0 = Ag + (size_t)r0 * lda + kb0 * 8;
    const __half* gB0 = Bg + (size_t)r0 * ldb + kb0 * 8;
    const size_t a64 = (size_t)64 * lda, b64 = (size_t)64 * ldb;
    const uint32_t sA0 = aSm + swz(r0, kb0),      sA1 = aSm + swz(r0 + 64, kb0);
    const uint32_t sB0 = bSm + swz(r0, kb0),      sB1 = bSm + swz(r0 + 64, kb0);

    uint32_t offA[4][2], offB[2][2];
    {
        int rl = (lane & 7) + ((lane >> 3) & 1) * 8;
        int ka = lane >> 4;
        #pragma unroll
        for (int mt = 0; mt < 4; mt++)
            #pragma unroll
            for (int t = 0; t < 2; t++)
                offA[mt][t] = swz(warpM + mt * 16 + rl, 2 * t + ka);
        int rb = (lane & 7) + ((lane >> 4) & 1) * 8;
        int kbb = (lane >> 3) & 1;
        #pragma unroll
        for (int p = 0; p < 2; p++)
            #pragma unroll
            for (int t = 0; t < 2; t++)
                offB[p][t] = swz(warpN + p * 16 + rb, 2 * t + kbb);
    }

#define ISSUE_STAGE(S) do {                                           \
        int _s = (S);                                                 \
        if (_s < NK) {                                                \
            const __half* _ga = gA0 + _s * 32;                        \
            const __half* _gb = gB0 + _s * 32;                        \
            uint32_t _so = (uint32_t)(_s & 3) * STAGEB;               \
            cpa16(sA0 + _so, _ga); cpa16(sA1 + _so, _ga + a64);       \
            cpa16(sB0 + _so, _gb); cpa16(sB1 + _so, _gb + b64);       \
        }                                                             \
        asm volatile("cp.async.commit_group;");                       \
    } while (0)

    __syncthreads();   // smem may be in use by a previous call
    ISSUE_STAGE(0);
    ISSUE_STAGE(1);
    ISSUE_STAGE(2);

    #pragma unroll
    for (int kt = 0; kt < NK; kt++) {
        asm volatile("cp.async.wait_group 2;");
        __syncthreads();
        ISSUE_STAGE(kt + 3);

        const uint32_t as_ = aSm + (uint32_t)(kt & 3) * STAGEB;
        const uint32_t bs_ = bSm + (uint32_t)(kt & 3) * STAGEB;
        #pragma unroll
        for (int t = 0; t < 2; t++) {
            uint32_t af[4][4], bf[2][4];
            #pragma unroll
            for (int mt = 0; mt < 4; mt++) ldsm_x4(af[mt], as_ + offA[mt][t]);
            #pragma unroll
            for (int p = 0; p < 2; p++)    ldsm_x4(bf[p],  bs_ + offB[p][t]);
            #pragma unroll
            for (int mt = 0; mt < 4; mt++)
                #pragma unroll
                for (int nt = 0; nt < 4; nt++)
                    mma_f16(acc[mt][nt], af[mt],
                            bf[nt >> 1][(nt & 1) * 2], bf[nt >> 1][(nt & 1) * 2 + 1]);
        }
    }
#undef ISSUE_STAGE
}

// ---------------- GEMM1: fused qkv + lite projections, fp16 scatter epilogue ----------------
__global__ __launch_bounds__(256, 2)
void gemm1_kernel(const float* __restrict__ qkv_b) {
    __shared__ __align__(128) char smA[4 * STAGEB];
    __shared__ __align__(128) char smB[4 * STAGEB];
    const uint32_t aSm = (uint32_t)__cvta_generic_to_shared(smA);
    const uint32_t bSm = (uint32_t)__cvta_generic_to_shared(smB);
    const int m0 = blockIdx.y * 128;
    const int n0 = blockIdx.x * 128;

    float acc[4][4][4] = {};
    mma_tile_cp<DIMC / 32>(g_x16 + (size_t)m0 * DIMC, DIMC,
                           g_wB + (size_t)n0 * DIMC, DIMC, acc, aSm, bSm);

    const int lane = threadIdx.x & 31, warp = threadIdx.x >> 5;
    const int warpM = (warp >> 2) * 64, warpN = (warp & 3) * 32;
    const int row = lane >> 2, tg2 = (lane & 3) * 2;
    const bool is_qkv = (n0 < 1536);

    #pragma unroll
    for (int mt = 0; mt < 4; mt++) {
        #pragma unroll
        for (int half = 0; half < 2; half++) {
            int m = m0 + warpM + mt * 16 + row + half * 8;
            int b = m / NTOK, n = m - b * NTOK;
            #pragma unroll
            for (int nt = 0; nt < 4; nt++) {
                int c = n0 + warpN + nt * 8 + tg2;
                float v0 = acc[mt][nt][half * 2 + 0];
                float v1 = acc[mt][nt][half * 2 + 1];
                if (is_qkv) {
                    v0 += qkv_b[c];
                    v1 += qkv_b[c + 1];
                    int jj = c >> 9, hh = (c >> 5) & 15, d = c & 31;
                    __half* dst = (jj == 0) ? g_q16 : ((jj == 1) ? g_k16 : g_v16);
                    __half2 hv = __floats2half2_rn(v0, v1);
                    *(__half2*)&dst[((size_t)(b * NHEADS + hh) * NTOK + n) * HD + d] = hv;
                } else {
                    int cc = c - 1536;
                    int jj = cc >> 7, hh = (cc >> 3) & 15, d = cc & 7;
                    __half* dst = (jj == 0) ? g_ql16 : ((jj == 1) ? g_kl16 : g_vl16);
                    __half2 hv = __floats2half2_rn(v0, v1);
                    *(__half2*)&dst[((size_t)(b * NHEADS + hh) * NTOK + n) * LHD + d] = hv;
                }
            }
        }
    }
}

// ---------------- fused dual attention with tensor cores, one block per (b,h) ----------------
// Tile offsets inside smT (all 1024-aligned-ish, 16B aligned at least):
#define OFF_Q   0        // 64 rows x 64B (swz)
#define OFF_K   4096
#define OFF_QL  8192
#define OFF_KL  12288
#define OFF_VT  16384    // 32 rows x 128B (sw128)  Vt[d][j]
#define OFF_VLT 20480    // 16 rows x 128B          Vlt[d][j]
#define OFF_PH  22528    // 64 rows x 128B          P fp16 (normalized)
#define OFF_WL  30720    // 64 rows x 128B          W fp16 (diff weights)
#define SMT_SZ  38912
#define SPST    56       // float stride of sp/spl rows

__global__ __launch_bounds__(256)
void attn_kernel(const float* __restrict__ mask,
                 const float* __restrict__ lam1p,
                 const float* __restrict__ lam2p) {
    __shared__ __align__(1024) char smT[SMT_SZ];
    __shared__ float sp [NTOK * SPST];
    __shared__ float spl[NTOK * SPST];
    __shared__ float sinv[2 * NTOK];

    const int bid = blockIdx.x;
    const int b = bid >> 4, h = bid & 15;
    const int win = b & (NWIN - 1);
    const int tid = threadIdx.x;
    const int warp = tid >> 5, lane = tid & 31;
    const uint32_t sb = (uint32_t)__cvta_generic_to_shared(smT);

    const __half* gq  = g_q16  + (size_t)bid * (NTOK * HD);
    const __half* gk  = g_k16  + (size_t)bid * (NTOK * HD);
    const __half* gv  = g_v16  + (size_t)bid * (NTOK * HD);
    const __half* gql = g_ql16 + (size_t)bid * (NTOK * LHD);
    const __half* gkl = g_kl16 + (size_t)bid * (NTOK * LHD);
    const __half* gvl = g_vl16 + (size_t)bid * (NTOK * LHD);

    // ---- fills ----
    {   // Q/K: one 16B chunk per thread per tile (64 rows x 4 octets)
        int j = tid >> 2, kb = tid & 3;
        uint4 qv = make_uint4(0, 0, 0, 0), kv = make_uint4(0, 0, 0, 0);
        if (j < NTOK) {
            qv = ((const uint4*)gq)[j * 4 + kb];
            kv = ((const uint4*)gk)[j * 4 + kb];
        }
        *(uint4*)(smT + OFF_Q + swz(j, kb)) = qv;
        *(uint4*)(smT + OFF_K + swz(j, kb)) = kv;
    }
    if (tid < 128) {   // lite tiles: octets 0 (data) and 1 (zero k-pad)
        int j = tid >> 1, oc = tid & 1;
        uint4 v1 = make_uint4(0, 0, 0, 0), v2 = make_uint4(0, 0, 0, 0);
        if (oc == 0 && j < NTOK) {
            v1 = ((const uint4*)gql)[j];
            v2 = ((const uint4*)gkl)[j];
        }
        *(uint4*)(smT + OFF_QL + swz(j, oc)) = v1;
        *(uint4*)(smT + OFF_KL + swz(j, oc)) = v2;
    }
    // Vt transpose fill: Vt[d][j] from gv[j][d]
    for (int idx = tid; idx < NTOK * 16; idx += 256) {
        int j = idx >> 4, d = (idx & 15) * 2;
        uint32_t v = ((const uint32_t*)gv)[idx];
        *(uint16_t*)(smT + OFF_VT + sw128h(d,     j)) = (uint16_t)(v & 0xffff);
        *(uint16_t*)(smT + OFF_VT + sw128h(d + 1, j)) = (uint16_t)(v >> 16);
    }
    for (int idx = tid; idx < 32 * 15; idx += 256) {   // Vt j-pads (j=49..63)
        int d = idx / 15, j = NTOK + idx % 15;
        *(uint16_t*)(smT + OFF_VT + sw128h(d, j)) = 0;
    }
    if (tid < NTOK * 4) {   // Vlt rows 0-7 fill
        int j = tid >> 2, d = (tid & 3) * 2;
        uint32_t v = ((const uint32_t*)gvl)[tid];
        *(uint16_t*)(smT + OFF_VLT + sw128h(d,     j)) = (uint16_t)(v & 0xffff);
        *(uint16_t*)(smT + OFF_VLT + sw128h(d + 1, j)) = (uint16_t)(v >> 16);
    }
    if (tid < 64) {   // Vlt n-pad rows 8-15: zero whole rows
        int r = 8 + (tid >> 3), oc = tid & 7;
        *(uint4*)(smT + OFF_VLT + sw128(r, oc)) = make_uint4(0, 0, 0, 0);
    }
    if (tid < 8 * 15) {   // Vlt j-pads rows 0-7
        int d = tid / 15, j = NTOK + tid % 15;
        *(uint16_t*)(smT + OFF_VLT + sw128h(d, j)) = 0;
    }
    __syncthreads();

    // ---- QK via mma: S[64x56], warp layout: mt = warp&3; warps 0-3: nt 0-3, warps 4-7: nt 4-6 ----
    const int mt = warp & 3;
    const int hi = warp >> 2;
    const int ntBase = hi * 4;
    const int ntCnt = hi ? 3 : 4;
    const int p0 = hi * 2;
    const int rl = (lane & 7) + ((lane >> 3) & 1) * 8, ka = lane >> 4;
    const int rb = (lane & 7) + ((lane >> 4) & 1) * 8, kbb = (lane >> 3) & 1;

    float accS[4][4] = {};
    float accL[4][4] = {};
    #pragma unroll
    for (int t = 0; t < 2; t++) {
        uint32_t af[4], bf[2][4];
        ldsm_x4(af,    sb + OFF_Q + swz(mt * 16 + rl, 2 * t + ka));
        ldsm_x4(bf[0], sb + OFF_K + swz(p0 * 16 + rb, 2 * t + kbb));
        ldsm_x4(bf[1], sb + OFF_K + swz((p0 + 1) * 16 + rb, 2 * t + kbb));
        #pragma unroll
        for (int l = 0; l < 4; l++) {
            if (l < ntCnt) {
                int nt = ntBase + l;
                mma_f16(accS[l], af, bf[(nt >> 1) - p0][(nt & 1) * 2],
                                     bf[(nt >> 1) - p0][(nt & 1) * 2 + 1]);
            }
        }
    }
    {   // lite branch: single k16 tile (upper 8 dims zero-padded)
        uint32_t af[4], bf[2][4];
        ldsm_x4(af,    sb + OFF_QL + swz(mt * 16 + rl, ka));
        ldsm_x4(bf[0], sb + OFF_KL + swz(p0 * 16 + rb, kbb));
        ldsm_x4(bf[1], sb + OFF_KL + swz((p0 + 1) * 16 + rb, kbb));
        #pragma unroll
        for (int l = 0; l < 4; l++) {
            if (l < ntCnt) {
                int nt = ntBase + l;
                mma_f16(accL[l], af, bf[(nt >> 1) - p0][(nt & 1) * 2],
                                     bf[(nt >> 1) - p0][(nt & 1) * 2 + 1]);
            }
        }
    }
    // S epilogue: scale + bias + mask, predicated rows < 49 (cols 49-55 garbage, zeroed later)
    {
        const float scale   = 0.17677669529663687f;   // 32^-0.5
        const float scale_l = 0.35355339059327373f;   // 8^-0.5
        const float* bias_h = g_relbias + h * NNSQ;
        const float* mask_w = mask + win * NNSQ;
        const int r0r = mt * 16 + (lane >> 2);
        #pragma unroll
        for (int l = 0; l < 4; l++) {
            if (l < ntCnt) {
                int c = (ntBase + l) * 8 + (lane & 3) * 2;
                int jc0 = min(c, NTOK - 1), jc1 = min(c + 1, NTOK - 1);
                if (r0r < NTOK) {
                    float bm0 = bias_h[r0r * NTOK + jc0] + mask_w[r0r * NTOK + jc0];
                    float bm1 = bias_h[r0r * NTOK + jc1] + mask_w[r0r * NTOK + jc1];
                    *(float2*)&sp [r0r * SPST + c] =
                        make_float2(accS[l][0] * scale + bm0, accS[l][1] * scale + bm1);
                    *(float2*)&spl[r0r * SPST + c] =
                        make_float2(accL[l][0] * scale_l + bm0, accL[l][1] * scale_l + bm1);
                }
                if (r0r + 8 < NTOK) {
                    int r1 = r0r + 8;
                    float bm0 = bias_h[r1 * NTOK + jc0] + mask_w[r1 * NTOK + jc0];
                    float bm1 = bias_h[r1 * NTOK + jc1] + mask_w[r1 * NTOK + jc1];
                    *(float2*)&sp [r1 * SPST + c] =
                        make_float2(accS[l][2] * scale + bm0, accS[l][3] * scale + bm1);
                    *(float2*)&spl[r1 * SPST + c] =
                        make_float2(accL[l][2] * scale_l + bm0, accL[l][3] * scale_l + bm1);
                }
            }
        }
    }
    __syncthreads();

    // ---- softmax: 2 lanes per row, exp in place + 1/sum ----
    if (tid < 2 * NTOK * 2) {
        int g = tid >> 1, q = tid & 1;
        float* row = ((g < NTOK) ? sp + g * SPST : spl + (g - NTOK) * SPST);
        unsigned am = __activemask();
        float mx = -1e30f;
        for (int j = q; j < NTOK; j += 2) mx = fmaxf(mx, row[j]);
        mx = fmaxf(mx, __shfl_xor_sync(am, mx, 1));
        float s = 0.f;
        for (int j = q; j < NTOK; j += 2) {
            float e = __expf(row[j] - mx);
            row[j] = e;
            s += e;
        }
        s += __shfl_xor_sync(am, s, 1);
        if (q == 0) sinv[g] = 1.f / s;
    }
    __syncthreads();

    // ---- build fp16 P (normalized) and W (diff weights) tiles, zero-padded to 64x64 ----
    {
        const float lam1 = 1.f / (1.f + __expf(-*lam1p));
        const float lam2 = 1.f / (1.f + __expf(-*lam2p));
        for (int idx = tid; idx < 512; idx += 256) {
            int i = idx >> 3, oct = idx & 7;
            float si = 0.f, c1 = 0.f, c2 = 0.f;
            if (i < NTOK) {
                si = sinv[i];
                c1 = lam1 * sinv[NTOK + i];
                c2 = lam2 * sinv[i];
            }
            uint32_t phk[4], wlk[4];
            #pragma unroll
            for (int q = 0; q < 4; q++) {
                int ca = oct * 8 + q * 2;
                float pa = 0.f, pb = 0.f, pla = 0.f, plb = 0.f;
                if (i < NTOK) {
                    if (ca < NTOK)     { pa = sp[i * SPST + ca];     pla = spl[i * SPST + ca]; }
                    if (ca + 1 < NTOK) { pb = sp[i * SPST + ca + 1]; plb = spl[i * SPST + ca + 1]; }
                }
                __half2 hp = __floats2half2_rn(pa * si, pb * si);
                __half2 hw = __floats2half2_rn(c1 * pla - c2 * pa, c1 * plb - c2 * pb);
                phk[q] = *(uint32_t*)&hp;
                wlk[q] = *(uint32_t*)&hw;
            }
            *(uint4*)(smT + OFF_PH + sw128(i, oct)) = make_uint4(phk[0], phk[1], phk[2], phk[3]);
            *(uint4*)(smT + OFF_WL + sw128(i, oct)) = make_uint4(wlk[0], wlk[1], wlk[2], wlk[3]);
        }
    }
    __syncthreads();

    // ---- PV main: out[64x32] = P[64x64(k)] x Vt; warp: mt = warp&3, d-half = hi ----
    {
        float om[2][4] = {};
        #pragma unroll
        for (int t = 0; t < 4; t++) {
            uint32_t af[4], bf[4];
            ldsm_x4(af, sb + OFF_PH + sw128(mt * 16 + rl, 2 * t + ka));
            ldsm_x4(bf, sb + OFF_VT + sw128(hi * 16 + rb, 2 * t + kbb));
            mma_f16(om[0], af, bf[0], bf[1]);
            mma_f16(om[1], af, bf[2], bf[3]);
        }
        int r = mt * 16 + (lane >> 2);
        int d0 = hi * 16 + (lane & 3) * 2;
        if (r < NTOK) {
            __half* dp = g_xo16 + ((size_t)(b * NTOK + r)) * DIMC + h * HD;
            *(__half2*)&dp[d0]     = __floats2half2_rn(om[0][0], om[0][1]);
            *(__half2*)&dp[d0 + 8] = __floats2half2_rn(om[1][0], om[1][1]);
        }
        if (r + 8 < NTOK) {
            __half* dp = g_xo16 + ((size_t)(b * NTOK + r + 8)) * DIMC + h * HD;
            *(__half2*)&dp[d0]     = __floats2half2_rn(om[0][2], om[0][3]);
            *(__half2*)&dp[d0 + 8] = __floats2half2_rn(om[1][2], om[1][3]);
        }
    }

    // ---- PV diff: dv[64x8] = W x Vlt; warps 4-7 (mt = warp&3) ----
    if (hi) {
        float od[4] = {};
        #pragma unroll
        for (int t = 0; t < 4; t++) {
            uint32_t af[4], bf[4];
            ldsm_x4(af, sb + OFF_WL + sw128(mt * 16 + rl, 2 * t + ka));
            ldsm_x4(bf, sb + OFF_VLT + sw128(rb, 2 * t + kbb));
            mma_f16(od, af, bf[0], bf[1]);
        }
        int r = mt * 16 + (lane >> 2);
        int d0 = (lane & 3) * 2;
        if (r < NTOK) {
            *(__half2*)&g_dv16[((size_t)(b * NTOK + r)) * LDIM + h * LHD + d0] =
                __floats2half2_rn(od[0], od[1]);
        }
        if (r + 8 < NTOK) {
            *(__half2*)&g_dv16[((size_t)(b * NTOK + r + 8)) * LDIM + h * LHD + d0] =
                __floats2half2_rn(od[2], od[3]);
        }
    }
}

// ---------------- GEMM3: out = xo@Wp^T + dv@W2t^T + b2 ----------------
__global__ __launch_bounds__(256, 2)
void gemm3_kernel(float* __restrict__ out) {
    __shared__ __align__(128) char smA[4 * STAGEB];
    __shared__ __align__(128) char smB[4 * STAGEB];
    const uint32_t aSm = (uint32_t)__cvta_generic_to_shared(smA);
    const uint32_t bSm = (uint32_t)__cvta_generic_to_shared(smB);
    const int m0 = blockIdx.y * 128;
    const int n0 = blockIdx.x * 128;

    float acc[4][4][4] = {};
    mma_tile_cp<DIMC / 32>(g_xo16 + (size_t)m0 * DIMC, DIMC,
                           g_pw16 + (size_t)n0 * DIMC, DIMC, acc, aSm, bSm);
    mma_tile_cp<LDIM / 32>(g_dv16 + (size_t)m0 * LDIM, LDIM,
                           g_W2t16 + (size_t)n0 * LDIM, LDIM, acc, aSm, bSm);

    const int lane = threadIdx.x & 31, warp = threadIdx.x >> 5;
    const int warpM = (warp >> 2) * 64, warpN = (warp & 3) * 32;
    const int row = lane >> 2, tg2 = (lane & 3) * 2;

    #pragma unroll
    for (int nt = 0; nt < 4; nt++) {
        int c = n0 + warpN + nt * 8 + tg2;
        float b0 = g_b2[c], b1 = g_b2[c + 1];
        #pragma unroll
        for (int mt = 0; mt < 4; mt++) {
            #pragma unroll
            for (int half = 0; half < 2; half++) {
                int m = m0 + warpM + mt * 16 + row + half * 8;
                *(float2*)&out[(size_t)m * DIMC + c] =
                    make_float2(acc[mt][nt][half * 2 + 0] + b0,
                                acc[mt][nt][half * 2 + 1] + b1);
            }
        }
    }
}

// ---------------- launch ----------------
extern "C" void kernel_launch(void* const* d_in, const int* in_sizes, int n_in,
                              void* d_out, int out_size) {
    const float* x       = (const float*)d_in[0];
    const float* mask    = (const float*)d_in[1];
    const int*   rpi     = (const int*)  d_in[2];
    const float* table   = (const float*)d_in[3];
    const float* qkv_w   = (const float*)d_in[4];
    const float* qkv_b   = (const float*)d_in[5];
    const float* proj_w  = (const float*)d_in[6];
    const float* proj_b  = (const float*)d_in[7];
    const float* qlw     = (const float*)d_in[8];
    const float* klw     = (const float*)d_in[9];
    const float* vlw     = (const float*)d_in[10];
    const float* lam1p   = (const float*)d_in[11];
    const float* lam2p   = (const float*)d_in[12];
    const float* dpw     = (const float*)d_in[13];
    const float* dpb     = (const float*)d_in[14];
    const float* gamma_p = (const float*)d_in[15];
    float* out = (float*)d_out;

    conv_x_kernel<<<(int)((size_t)MROWS * DIMC / 4 / 256), 256>>>(x);
    conv_wB_kernel<<<NCOLS1 * DIMC / 4 / 256, 256>>>(qkv_w, qlw, klw, vlw);
    conv_pw_kernel<<<DIMC * DIMC / 4 / 256, 256>>>(proj_w);
    prep_bias_kernel<<<(NHEADS * NNSQ + 255) / 256, 256>>>(rpi, table);
    prep_w2_kernel<<<DIMC, LDIM>>>(dpw, proj_w, gamma_p);

    gemm1_kernel<<<dim3(NCOLS1 / 128, MROWS / 128), 256>>>(qkv_b);

    prep_b2_kernel<<<2, 256>>>(dpb, proj_w, proj_b, gamma_p);
    attn_kernel<<<NB * NHEADS, 256>>>(mask, lam1p, lam2p);
    gemm3_kernel<<<dim3(4, MROWS / 128), 256>>>(out);
}